// round 12
// baseline (speedup 1.0000x reference)
#include <cuda.h>
#include <cuda_runtime.h>
#include <cuda_bf16.h>
#include <math.h>
#include <stdint.h>

#define B_ 64
#define L_ 256
#define D_ 128
#define N_ 8192
#define KEEP_ 64
#define HID_ 1024
#define KTOT 8320
#define BM 128
#define BN 64
#define BK 128
#define STAGES 4
#define KITER 65            // KTOT / BK
// stage: A1 16KB, A0 16KB, B1 8KB, B0 8KB
#define STG_BYTES 49152
#define A1_OFF 0
#define A0_OFF 16384
#define B1_OFF 32768
#define B0_OFF 40960
#define DATA_BYTES (STAGES * STG_BYTES)
#define SMEM_ALLOC (DATA_BYTES + 1024 + 128)
#define NT_ (HID_ / BN)     // 16 n-tiles

__device__ __align__(1024) signed char g_f1[(size_t)N_ * KTOT];
__device__ __align__(1024) signed char g_f0[(size_t)N_ * KTOT];
__device__ __align__(1024) signed char g_w1q[(size_t)HID_ * KTOT];
__device__ __align__(1024) signed char g_w0q[(size_t)HID_ * KTOT];
__device__ int   g_idx[N_ * KEEP_];
__device__ float g_part2[NT_ * N_];
__device__ int   g_mask_mode;

// ---------------- PTX helpers ----------------
__device__ __forceinline__ uint32_t smem_to_u32(const void* p) {
    uint32_t a;
    asm("{ .reg .u64 t; cvta.to.shared.u64 t, %1; cvt.u32.u64 %0, t; }" : "=r"(a) : "l"(p));
    return a;
}
#define MBAR_INIT(a, c) asm volatile("mbarrier.init.shared.b64 [%0], %1;" :: "r"((uint32_t)(a)), "r"((uint32_t)(c)) : "memory")
#define MBAR_EXPECT(a, b) asm volatile("mbarrier.arrive.expect_tx.shared.b64 _, [%0], %1;" :: "r"((uint32_t)(a)), "r"((uint32_t)(b)) : "memory")
#define MBAR_WAIT(a, p) do { \
    uint32_t _m=(uint32_t)(a), _p=(uint32_t)(p); \
    asm volatile("{\n.reg .pred P;\nW%=:\nmbarrier.try_wait.parity.acquire.cta.shared::cta.b64 P, [%0], %1, 0x989680;\n@P bra.uni D%=;\nbra.uni W%=;\nD%=:\n}" :: "r"(_m), "r"(_p) : "memory"); \
} while(0)
#define FENCE_ASYNC() asm volatile("fence.proxy.async.shared::cta;" ::: "memory")
#define TMA_2D(dst, map, cx, cy, mbar) \
    asm volatile("cp.async.bulk.tensor.2d.shared::cta.global.tile.mbarrier::complete_tx::bytes " \
        "[%0], [%1, {%2, %3}], [%4];" \
        :: "r"((uint32_t)(dst)), "l"(map), "r"((int32_t)(cx)), "r"((int32_t)(cy)), "r"((uint32_t)(mbar)) : "memory")

__device__ __forceinline__ void ldsm4(uint32_t* r, uint32_t addr) {
    asm volatile("ldmatrix.sync.aligned.m8n8.x4.shared.b16 {%0,%1,%2,%3}, [%4];"
        : "=r"(r[0]), "=r"(r[1]), "=r"(r[2]), "=r"(r[3]) : "r"(addr));
}
__device__ __forceinline__ void mma_s8(int* d, const uint32_t* a, const uint32_t* b) {
    asm volatile("mma.sync.aligned.m16n8k32.row.col.s32.s8.s8.s32 "
        "{%0,%1,%2,%3}, {%4,%5,%6,%7}, {%8,%9}, {%0,%1,%2,%3};"
        : "+r"(d[0]), "+r"(d[1]), "+r"(d[2]), "+r"(d[3])
        : "r"(a[0]), "r"(a[1]), "r"(a[2]), "r"(a[3]), "r"(b[0]), "r"(b[1]));
}
// SW128: 16B chunk c (0..7) in a 128B row, tile 1KB-aligned -> c ^= (row & 7)
__device__ __forceinline__ uint32_t swz(int row, int c) {
    return (uint32_t)(row * 128 + ((c ^ (row & 7)) << 4));
}
__device__ __forceinline__ float gelu_exact(float x) {
    return 0.5f * x * (1.0f + erff(x * 0.7071067811865476f));
}
// fixed-point split with per-matrix scale: v_q = v1*256 + v0, both s8, exact
__device__ __forceinline__ void quant_split(float v, float scale, signed char* c1, signed char* c0) {
    int aq = __float2int_rn(v * scale);
    aq = max(-32768, min(32639, aq));
    int a1 = (aq + 128) >> 8;
    *c1 = (signed char)a1;
    *c0 = (signed char)(aq - (a1 << 8));
}

// ---------------- small kernels (proven) ----------------
__global__ void detect_mask_kernel(const unsigned int* __restrict__ mw) {
    if (threadIdx.x | blockIdx.x) return;
    bool i32ok = true, f32ok = true;
    for (int i = 0; i < 1024; i++) {
        unsigned w = mw[i];
        if (!(w == 0u || w == 1u)) i32ok = false;
        if (!(w == 0u || w == 0x3F800000u)) f32ok = false;
    }
    g_mask_mode = i32ok ? 1 : (f32ok ? 2 : 0);
}

__global__ void gather_idx_kernel(const void* __restrict__ maskp) {
    int gw = (blockIdx.x * blockDim.x + threadIdx.x) >> 5, lane = threadIdx.x & 31;
    if (gw >= N_) return;
    const int n = gw;
    g_idx[n * KEEP_ + lane] = -1;
    g_idx[n * KEEP_ + 32 + lane] = -1;
    __syncwarp();
    const int mode = g_mask_mode;
    const unsigned char* m8 = (const unsigned char*)maskp;
    const int* m32 = (const int*)maskp;
    const float* mf = (const float*)maskp;
    int base = 0;
    for (int g = 0; g < 8 && base < KEEP_; g++) {
        int pos = g * 32 + lane;
        bool m;
        if (mode == 1)      m = (m32[(size_t)n * L_ + pos] != 0);
        else if (mode == 2) m = (mf [(size_t)n * L_ + pos] != 0.0f);
        else                m = (m8 [(size_t)n * L_ + pos] != 0);
        unsigned bal = __ballot_sync(0xffffffffu, m);
        int slot = base + __popc(bal & ((1u << lane) - 1u));
        if (m && slot < KEEP_) g_idx[n * KEEP_ + slot] = pos;
        base += __popc(bal);
    }
}

__global__ void __launch_bounds__(256)
convert_feat_kernel(const float* __restrict__ q, const float* __restrict__ kmat,
                    const int* __restrict__ bidx) {
    int row = blockIdx.x;
    const int* idxr = g_idx + row * KEEP_;
    const float* kbase = kmat + (size_t)bidx[row] * (L_ * D_);
    size_t ro = (size_t)row * KTOT;
    for (int pos = threadIdx.x; pos < KTOT; pos += 256) {
        float v;
        if (pos < D_) v = q[(size_t)row * D_ + pos];
        else {
            int j = (pos - D_) >> 7, d = (pos - D_) & 127;
            int ix = idxr[j];
            v = (ix >= 0) ? kbase[(size_t)ix * D_ + d] : 0.0f;
        }
        quant_split(v, 4096.0f, &g_f1[ro + pos], &g_f0[ro + pos]);   // 2^12
    }
}

__global__ void __launch_bounds__(256)
convert_w1_kernel(const float* __restrict__ W1) {
    __shared__ float t[32][33];
    int k0 = blockIdx.x * 32, n0 = blockIdx.y * 32;
    int tx = threadIdx.x, ty = threadIdx.y;  // 32 x 8
#pragma unroll
    for (int i = 0; i < 4; i++)
        t[ty + i * 8][tx] = W1[(size_t)(k0 + ty + i * 8) * HID_ + n0 + tx];
    __syncthreads();
#pragma unroll
    for (int i = 0; i < 4; i++) {
        int r = ty + i * 8;
        float v = t[tx][r];
        size_t o = (size_t)(n0 + r) * KTOT + k0 + tx;
        quant_split(v, 262144.0f, &g_w1q[o], &g_w0q[o]);             // 2^18
    }
}

// ---------------- int8 4-term exact GEMM, TMA-fed ----------------
__global__ void __launch_bounds__(256, 1)
gemm_kernel(const __grid_constant__ CUtensorMap tm_a1,
            const __grid_constant__ CUtensorMap tm_a0,
            const __grid_constant__ CUtensorMap tm_b1,
            const __grid_constant__ CUtensorMap tm_b0,
            const float* __restrict__ W1, const float* __restrict__ b1,
            const float* __restrict__ W2, const int* __restrict__ count)
{
    extern __shared__ char smem[];
    const uint32_t sb = smem_to_u32(smem);
    const uint32_t db = (sb + 1023u) & ~1023u;
    const uint32_t mb = db + DATA_BYTES;                // 4 full mbarriers
    const int tid = threadIdx.x, lane = tid & 31, wid = tid >> 5;
    const int wm = wid >> 1, wn = wid & 1;              // 4 x 2 warps, 32x32 tiles
    const int m0 = blockIdx.y * BM, n0 = blockIdx.x * BN;

    if (tid == 0) {
#pragma unroll
        for (int s = 0; s < STAGES; s++) MBAR_INIT(mb + s * 8, 1);
        FENCE_ASYNC();
    }
    __syncthreads();

    if (tid == 0) {
#pragma unroll
        for (int s = 0; s < STAGES; s++) {
            uint32_t st = db + s * STG_BYTES;
            MBAR_EXPECT(mb + s * 8, STG_BYTES);
            TMA_2D(st + A1_OFF, &tm_a1, s * BK, m0, mb + s * 8);
            TMA_2D(st + A0_OFF, &tm_a0, s * BK, m0, mb + s * 8);
            TMA_2D(st + B1_OFF, &tm_b1, s * BK, n0, mb + s * 8);
            TMA_2D(st + B0_OFF, &tm_b0, s * BK, n0, mb + s * 8);
        }
    }

    int hh[2][4][4], md[2][4][4], ll[2][4][4];
#pragma unroll
    for (int a = 0; a < 2; a++)
#pragma unroll
        for (int b = 0; b < 4; b++)
#pragma unroll
            for (int c = 0; c < 4; c++) { hh[a][b][c] = 0; md[a][b][c] = 0; ll[a][b][c] = 0; }

    for (int kt = 0; kt < KITER; kt++) {
        const int s = kt & 3;
        MBAR_WAIT(mb + s * 8, (kt >> 2) & 1);
        const uint32_t stg = db + s * STG_BYTES;

#pragma unroll
        for (int ks = 0; ks < 4; ks++) {                // k32 steps within BK=128
            uint32_t a1f[2][4], a0f[2][4], b1f[4][2], b0f[4][2];
            const int cb = ks * 2 + (lane >> 4);
#pragma unroll
            for (int mi = 0; mi < 2; mi++) {
                int row = wm * 32 + mi * 16 + (lane & 15);
                uint32_t off = swz(row, cb);
                ldsm4(a1f[mi], stg + A1_OFF + off);
                ldsm4(a0f[mi], stg + A0_OFF + off);
            }
#pragma unroll
            for (int nj = 0; nj < 2; nj++) {
                int row = wn * 32 + nj * 16 + (lane & 15);
                uint32_t off = swz(row, cb);
                uint32_t t[4];
                ldsm4(t, stg + B1_OFF + off);
                b1f[nj*2][0] = t[0]; b1f[nj*2][1] = t[2];
                b1f[nj*2+1][0] = t[1]; b1f[nj*2+1][1] = t[3];
                ldsm4(t, stg + B0_OFF + off);
                b0f[nj*2][0] = t[0]; b0f[nj*2][1] = t[2];
                b0f[nj*2+1][0] = t[1]; b0f[nj*2+1][1] = t[3];
            }

            if (ks == 3) {
                __syncthreads();        // stage consumed; refill overlaps mma
                if (tid == 0 && kt + STAGES < KITER) {
                    int kn = kt + STAGES;
                    uint32_t st = db + s * STG_BYTES;
                    MBAR_EXPECT(mb + s * 8, STG_BYTES);
                    TMA_2D(st + A1_OFF, &tm_a1, kn * BK, m0, mb + s * 8);
                    TMA_2D(st + A0_OFF, &tm_a0, kn * BK, m0, mb + s * 8);
                    TMA_2D(st + B1_OFF, &tm_b1, kn * BK, n0, mb + s * 8);
                    TMA_2D(st + B0_OFF, &tm_b0, kn * BK, n0, mb + s * 8);
                }
            }
#pragma unroll
            for (int mi = 0; mi < 2; mi++)
#pragma unroll
                for (int ni = 0; ni < 4; ni++) {
                    mma_s8(hh[mi][ni], a1f[mi], b1f[ni]);
                    mma_s8(md[mi][ni], a1f[mi], b0f[ni]);
                    mma_s8(md[mi][ni], a0f[mi], b1f[ni]);
                    mma_s8(ll[mi][ni], a0f[mi], b0f[ni]);
                }
        }
    }

    // ---- exact int64 fold, scale 2^-30; fused epilogue ----
    const int r = lane >> 2, c2 = (lane & 3) * 2;
    const float* wl = W1 + (size_t)8320 * HID_;
    const float INV = 9.313225746154785e-10f;   // 2^-30 = 2^-12 * 2^-18
    float pA[2], pB[2], lcA[2], lcB[2];
#pragma unroll
    for (int mi = 0; mi < 2; mi++) {
        int rowA = m0 + wm * 32 + mi * 16 + r;
        lcA[mi] = log1pf((float)count[rowA]);
        lcB[mi] = log1pf((float)count[rowA + 8]);
        pA[mi] = 0.0f; pB[mi] = 0.0f;
    }
#pragma unroll
    for (int ni = 0; ni < 4; ni++) {
        int n = n0 + wn * 32 + ni * 8 + c2;
        float b10 = b1[n], b11 = b1[n + 1];
        float wl0 = wl[n], wl1 = wl[n + 1];
        float w20 = W2[n], w21 = W2[n + 1];
#pragma unroll
        for (int mi = 0; mi < 2; mi++) {
            float z0 = (float)(((long long)hh[mi][ni][0] << 16)
                     + ((long long)md[mi][ni][0] << 8) + ll[mi][ni][0]) * INV;
            float z1 = (float)(((long long)hh[mi][ni][1] << 16)
                     + ((long long)md[mi][ni][1] << 8) + ll[mi][ni][1]) * INV;
            float z2 = (float)(((long long)hh[mi][ni][2] << 16)
                     + ((long long)md[mi][ni][2] << 8) + ll[mi][ni][2]) * INV;
            float z3 = (float)(((long long)hh[mi][ni][3] << 16)
                     + ((long long)md[mi][ni][3] << 8) + ll[mi][ni][3]) * INV;
            pA[mi] += gelu_exact(z0 + b10 + lcA[mi] * wl0) * w20
                    + gelu_exact(z1 + b11 + lcA[mi] * wl1) * w21;
            pB[mi] += gelu_exact(z2 + b10 + lcB[mi] * wl0) * w20
                    + gelu_exact(z3 + b11 + lcB[mi] * wl1) * w21;
        }
    }
#pragma unroll
    for (int mi = 0; mi < 2; mi++) {
        pA[mi] += __shfl_xor_sync(0xffffffffu, pA[mi], 1);
        pA[mi] += __shfl_xor_sync(0xffffffffu, pA[mi], 2);
        pB[mi] += __shfl_xor_sync(0xffffffffu, pB[mi], 1);
        pB[mi] += __shfl_xor_sync(0xffffffffu, pB[mi], 2);
    }
    __syncthreads();
    float* red = (float*)smem;          // [128 rows][2 wn]
    if ((lane & 3) == 0) {
#pragma unroll
        for (int mi = 0; mi < 2; mi++) {
            int rA = wm * 32 + mi * 16 + r;
            red[rA * 2 + wn]       = pA[mi];
            red[(rA + 8) * 2 + wn] = pB[mi];
        }
    }
    __syncthreads();
    if (tid < 128) {
        float sum = red[tid * 2] + red[tid * 2 + 1];
        g_part2[(size_t)blockIdx.x * N_ + m0 + tid] = sum;
    }
}

__global__ void final_kernel(const float* __restrict__ b2, float* __restrict__ out) {
    int i = blockIdx.x * 256 + threadIdx.x;
    float s = b2[0];
#pragma unroll
    for (int nb = 0; nb < NT_; nb++) s += g_part2[(size_t)nb * N_ + i];
    out[i] = s;
}

// ---------------- host ----------------
typedef CUresult (CUDAAPI *EncodeFn)(
    CUtensorMap*, CUtensorMapDataType, cuuint32_t, void*,
    const cuuint64_t*, const cuuint64_t*, const cuuint32_t*, const cuuint32_t*,
    CUtensorMapInterleave, CUtensorMapSwizzle, CUtensorMapL2promotion, CUtensorMapFloatOOBfill);

static void encode2d(EncodeFn enc, CUtensorMap* m, void* ptr, uint64_t d0, uint64_t d1,
                     uint32_t rows) {
    cuuint64_t dims[2] = {d0, d1};
    cuuint64_t strides[1] = {d0};
    cuuint32_t box[2] = {128u, rows};   // 128B x rows, SW128
    cuuint32_t es[2] = {1u, 1u};
    enc(m, CU_TENSOR_MAP_DATA_TYPE_UINT8, 2, ptr, dims, strides, box, es,
        CU_TENSOR_MAP_INTERLEAVE_NONE, CU_TENSOR_MAP_SWIZZLE_128B,
        CU_TENSOR_MAP_L2_PROMOTION_L2_128B, CU_TENSOR_MAP_FLOAT_OOB_FILL_NONE);
}

extern "C" void kernel_launch(void* const* d_in, const int* in_sizes, int n_in,
                              void* d_out, int out_size) {
    const float* q     = (const float*)d_in[0];
    const float* k     = (const float*)d_in[1];
    const int*   bidx  = (const int*)d_in[2];
    const void*  mask  = d_in[3];
    const int*   count = (const int*)d_in[4];
    const float* W1    = (const float*)d_in[5];
    const float* b1    = (const float*)d_in[6];
    const float* W2    = (const float*)d_in[7];
    const float* b2    = (const float*)d_in[8];
    float* out = (float*)d_out;

    void* encp = nullptr;
    cudaDriverEntryPointQueryResult st;
    cudaGetDriverEntryPointByVersion("cuTensorMapEncodeTiled", &encp, 12000,
                                     cudaEnableDefault, &st);
    EncodeFn enc = (EncodeFn)encp;

    void *p_f1, *p_f0, *p_w1, *p_w0;
    cudaGetSymbolAddress(&p_f1, g_f1);
    cudaGetSymbolAddress(&p_f0, g_f0);
    cudaGetSymbolAddress(&p_w1, g_w1q);
    cudaGetSymbolAddress(&p_w0, g_w0q);

    CUtensorMap tm_a1, tm_a0, tm_b1, tm_b0;
    encode2d(enc, &tm_a1, p_f1, KTOT, N_, 128u);
    encode2d(enc, &tm_a0, p_f0, KTOT, N_, 128u);
    encode2d(enc, &tm_b1, p_w1, KTOT, HID_, 64u);
    encode2d(enc, &tm_b0, p_w0, KTOT, HID_, 64u);

    cudaFuncSetAttribute(gemm_kernel, cudaFuncAttributeMaxDynamicSharedMemorySize, SMEM_ALLOC);

    detect_mask_kernel<<<1, 32>>>((const unsigned int*)mask);
    gather_idx_kernel<<<N_ / 8, 256>>>(mask);
    convert_feat_kernel<<<N_, 256>>>(q, k, bidx);
    convert_w1_kernel<<<dim3(KTOT / 32, HID_ / 32), dim3(32, 8)>>>(W1);
    gemm_kernel<<<dim3(HID_ / BN, N_ / BM), 256, SMEM_ALLOC>>>(tm_a1, tm_a0, tm_b1, tm_b0,
                                                               W1, b1, W2, count);
    final_kernel<<<N_ / 256, 256>>>(b2, out);
}

// round 13
// speedup vs baseline: 7.8776x; 7.8776x over previous
#include <cuda.h>
#include <cuda_runtime.h>
#include <cuda_fp16.h>
#include <math.h>
#include <stdint.h>

#define B_ 64
#define L_ 256
#define D_ 128
#define N_ 8192
#define KEEP_ 64
#define HID_ 1024
#define KTOT 8320
#define BM 256
#define BN 128
#define BK 64
#define STAGES 4
#define KITER 130           // KTOT / BK
// stage: A 32KB, B 16KB
#define STG_BYTES 49152
#define A_OFF 0
#define B_OFF 32768
#define DATA_BYTES (STAGES * STG_BYTES)
#define SMEM_ALLOC (DATA_BYTES + 1024 + 128)

__device__ __align__(1024) __half g_feat[(size_t)N_ * KTOT];
__device__ __align__(1024) __half g_wt[(size_t)HID_ * KTOT];
__device__ int   g_idx[N_ * KEEP_];
__device__ float g_part2[8 * N_];
__device__ int   g_mask_mode;

// ---------------- PTX helpers ----------------
__device__ __forceinline__ uint32_t smem_to_u32(const void* p) {
    uint32_t a;
    asm("{ .reg .u64 t; cvta.to.shared.u64 t, %1; cvt.u32.u64 %0, t; }" : "=r"(a) : "l"(p));
    return a;
}
#define MBAR_INIT(a, c) asm volatile("mbarrier.init.shared.b64 [%0], %1;" :: "r"((uint32_t)(a)), "r"((uint32_t)(c)) : "memory")
#define MBAR_EXPECT(a, b) asm volatile("mbarrier.arrive.expect_tx.shared.b64 _, [%0], %1;" :: "r"((uint32_t)(a)), "r"((uint32_t)(b)) : "memory")
#define MBAR_WAIT(a, p) do { \
    uint32_t _m=(uint32_t)(a), _p=(uint32_t)(p); \
    asm volatile("{\n.reg .pred P;\nW%=:\nmbarrier.try_wait.parity.acquire.cta.shared::cta.b64 P, [%0], %1, 0x989680;\n@P bra.uni D%=;\nbra.uni W%=;\nD%=:\n}" :: "r"(_m), "r"(_p) : "memory"); \
} while(0)
#define FENCE_ASYNC() asm volatile("fence.proxy.async.shared::cta;" ::: "memory")
#define TMA_2D(dst, map, cx, cy, mbar) \
    asm volatile("cp.async.bulk.tensor.2d.shared::cta.global.tile.mbarrier::complete_tx::bytes " \
        "[%0], [%1, {%2, %3}], [%4];" \
        :: "r"((uint32_t)(dst)), "l"(map), "r"((int32_t)(cx)), "r"((int32_t)(cy)), "r"((uint32_t)(mbar)) : "memory")

__device__ __forceinline__ void ldsm4(uint32_t* r, uint32_t addr) {
    asm volatile("ldmatrix.sync.aligned.m8n8.x4.shared.b16 {%0,%1,%2,%3}, [%4];"
        : "=r"(r[0]), "=r"(r[1]), "=r"(r[2]), "=r"(r[3]) : "r"(addr));
}
__device__ __forceinline__ void mma_f16(float* d, const uint32_t* a, const uint32_t* b) {
    asm volatile("mma.sync.aligned.m16n8k16.row.col.f32.f16.f16.f32 "
        "{%0,%1,%2,%3}, {%4,%5,%6,%7}, {%8,%9}, {%0,%1,%2,%3};"
        : "+f"(d[0]), "+f"(d[1]), "+f"(d[2]), "+f"(d[3])
        : "r"(a[0]), "r"(a[1]), "r"(a[2]), "r"(a[3]), "r"(b[0]), "r"(b[1]));
}
// SW128: 16B chunk c (0..7) in a 128B row, tile 1KB-aligned -> c ^= (row & 7)  (R7/R8-proven)
__device__ __forceinline__ uint32_t swz(int row, int c) {
    return (uint32_t)(row * 128 + ((c ^ (row & 7)) << 4));
}
__device__ __forceinline__ float gelu_exact(float x) {
    return 0.5f * x * (1.0f + erff(x * 0.7071067811865476f));
}

// ---------------- small kernels (proven) ----------------
__global__ void detect_mask_kernel(const unsigned int* __restrict__ mw) {
    if (threadIdx.x | blockIdx.x) return;
    bool i32ok = true, f32ok = true;
    for (int i = 0; i < 1024; i++) {
        unsigned w = mw[i];
        if (!(w == 0u || w == 1u)) i32ok = false;
        if (!(w == 0u || w == 0x3F800000u)) f32ok = false;
    }
    g_mask_mode = i32ok ? 1 : (f32ok ? 2 : 0);
}

__global__ void gather_idx_kernel(const void* __restrict__ maskp) {
    int gw = (blockIdx.x * blockDim.x + threadIdx.x) >> 5, lane = threadIdx.x & 31;
    if (gw >= N_) return;
    const int n = gw;
    g_idx[n * KEEP_ + lane] = -1;
    g_idx[n * KEEP_ + 32 + lane] = -1;
    __syncwarp();
    const int mode = g_mask_mode;
    const unsigned char* m8 = (const unsigned char*)maskp;
    const int* m32 = (const int*)maskp;
    const float* mf = (const float*)maskp;
    int base = 0;
    for (int g = 0; g < 8 && base < KEEP_; g++) {
        int pos = g * 32 + lane;
        bool m;
        if (mode == 1)      m = (m32[(size_t)n * L_ + pos] != 0);
        else if (mode == 2) m = (mf [(size_t)n * L_ + pos] != 0.0f);
        else                m = (m8 [(size_t)n * L_ + pos] != 0);
        unsigned bal = __ballot_sync(0xffffffffu, m);
        int slot = base + __popc(bal & ((1u << lane) - 1u));
        if (m && slot < KEEP_) g_idx[n * KEEP_ + slot] = pos;
        base += __popc(bal);
    }
}

__global__ void __launch_bounds__(256)
convert_feat_kernel(const float* __restrict__ q, const float* __restrict__ kmat,
                    const int* __restrict__ bidx) {
    int row = blockIdx.x;
    const int* idxr = g_idx + row * KEEP_;
    const float* kbase = kmat + (size_t)bidx[row] * (L_ * D_);
    size_t ro = (size_t)row * KTOT;
    for (int pos = threadIdx.x; pos < KTOT; pos += 256) {
        float v;
        if (pos < D_) v = q[(size_t)row * D_ + pos];
        else {
            int j = (pos - D_) >> 7, d = (pos - D_) & 127;
            int ix = idxr[j];
            v = (ix >= 0) ? kbase[(size_t)ix * D_ + d] : 0.0f;
        }
        g_feat[ro + pos] = __float2half_rn(v);
    }
}

__global__ void __launch_bounds__(256)
convert_w1_kernel(const float* __restrict__ W1) {
    __shared__ float t[32][33];
    int k0 = blockIdx.x * 32, n0 = blockIdx.y * 32;
    int tx = threadIdx.x, ty = threadIdx.y;  // 32 x 8
#pragma unroll
    for (int i = 0; i < 4; i++)
        t[ty + i * 8][tx] = W1[(size_t)(k0 + ty + i * 8) * HID_ + n0 + tx];
    __syncthreads();
#pragma unroll
    for (int i = 0; i < 4; i++) {
        int r = ty + i * 8;
        float v = t[tx][r];
        g_wt[(size_t)(n0 + r) * KTOT + k0 + tx] = __float2half_rn(v);
    }
}

// ---------------- single-pass fp16 mma.sync GEMM, TMA-fed ----------------
__global__ void __launch_bounds__(256, 1)
gemm_kernel(const __grid_constant__ CUtensorMap tm_a,
            const __grid_constant__ CUtensorMap tm_b,
            const float* __restrict__ W1, const float* __restrict__ b1,
            const float* __restrict__ W2, const int* __restrict__ count)
{
    extern __shared__ char smem[];
    const uint32_t sb = smem_to_u32(smem);
    const uint32_t db = (sb + 1023u) & ~1023u;          // data base, 1KB aligned
    const uint32_t mb = db + DATA_BYTES;                // 4 full mbarriers
    const int tid = threadIdx.x, lane = tid & 31, wid = tid >> 5;
    const int wm = wid >> 1, wn = wid & 1;              // 4 x 2 warps, 64x64 tiles
    const int m0 = blockIdx.y * BM, n0 = blockIdx.x * BN;

    if (tid == 0) {
#pragma unroll
        for (int s = 0; s < STAGES; s++) MBAR_INIT(mb + s * 8, 1);
        FENCE_ASYNC();
    }
    __syncthreads();

    if (tid == 0) {
#pragma unroll
        for (int s = 0; s < STAGES; s++) {
            uint32_t st = db + s * STG_BYTES;
            MBAR_EXPECT(mb + s * 8, STG_BYTES);
            TMA_2D(st + A_OFF, &tm_a, s * BK, m0, mb + s * 8);
            TMA_2D(st + B_OFF, &tm_b, s * BK, n0, mb + s * 8);
        }
    }

    float acc[4][8][4];
#pragma unroll
    for (int a = 0; a < 4; a++)
#pragma unroll
        for (int b = 0; b < 8; b++)
#pragma unroll
            for (int c = 0; c < 4; c++) acc[a][b][c] = 0.0f;

    for (int kt = 0; kt < KITER; kt++) {
        const int s = kt & 3;
        MBAR_WAIT(mb + s * 8, (kt >> 2) & 1);
        const uint32_t stg = db + s * STG_BYTES;

#pragma unroll
        for (int ks = 0; ks < 4; ks++) {                // k16 steps within BK=64
            uint32_t af[4][4], bf[8][2];
            const int cb = ks * 2 + (lane >> 4);
#pragma unroll
            for (int mi = 0; mi < 4; mi++) {
                int row = wm * 64 + mi * 16 + (lane & 15);
                ldsm4(af[mi], stg + A_OFF + swz(row, cb));
            }
#pragma unroll
            for (int nj = 0; nj < 4; nj++) {
                int row = wn * 64 + nj * 16 + (lane & 15);
                uint32_t t[4];
                ldsm4(t, stg + B_OFF + swz(row, cb));
                bf[nj*2][0] = t[0]; bf[nj*2][1] = t[2];
                bf[nj*2+1][0] = t[1]; bf[nj*2+1][1] = t[3];
            }

            if (ks == 3) {
                __syncthreads();        // stage consumed; refill overlaps mma
                if (tid == 0 && kt + STAGES < KITER) {
                    int kn = kt + STAGES;
                    uint32_t st = db + s * STG_BYTES;
                    MBAR_EXPECT(mb + s * 8, STG_BYTES);
                    TMA_2D(st + A_OFF, &tm_a, kn * BK, m0, mb + s * 8);
                    TMA_2D(st + B_OFF, &tm_b, kn * BK, n0, mb + s * 8);
                }
            }
#pragma unroll
            for (int mi = 0; mi < 4; mi++)
#pragma unroll
                for (int ni = 0; ni < 8; ni++)
                    mma_f16(acc[mi][ni], af[mi], bf[ni]);
        }
    }

    // ---- fused epilogue: z = acc + b1 + lc*W1[8320]; gelu(z)*W2 row-reduce ----
    const int r = lane >> 2, c2 = (lane & 3) * 2;
    const float* wl = W1 + (size_t)8320 * HID_;
    float pA[4], pB[4], lcA[4], lcB[4];
#pragma unroll
    for (int mi = 0; mi < 4; mi++) {
        int rowA = m0 + wm * 64 + mi * 16 + r;
        lcA[mi] = log1pf((float)count[rowA]);
        lcB[mi] = log1pf((float)count[rowA + 8]);
        pA[mi] = 0.0f; pB[mi] = 0.0f;
    }
#pragma unroll
    for (int ni = 0; ni < 8; ni++) {
        int n = n0 + wn * 64 + ni * 8 + c2;
        float b10 = b1[n], b11 = b1[n + 1];
        float wl0 = wl[n], wl1 = wl[n + 1];
        float w20 = W2[n], w21 = W2[n + 1];
#pragma unroll
        for (int mi = 0; mi < 4; mi++) {
            pA[mi] += gelu_exact(acc[mi][ni][0] + b10 + lcA[mi] * wl0) * w20
                    + gelu_exact(acc[mi][ni][1] + b11 + lcA[mi] * wl1) * w21;
            pB[mi] += gelu_exact(acc[mi][ni][2] + b10 + lcB[mi] * wl0) * w20
                    + gelu_exact(acc[mi][ni][3] + b11 + lcB[mi] * wl1) * w21;
        }
    }
#pragma unroll
    for (int mi = 0; mi < 4; mi++) {
        pA[mi] += __shfl_xor_sync(0xffffffffu, pA[mi], 1);
        pA[mi] += __shfl_xor_sync(0xffffffffu, pA[mi], 2);
        pB[mi] += __shfl_xor_sync(0xffffffffu, pB[mi], 1);
        pB[mi] += __shfl_xor_sync(0xffffffffu, pB[mi], 2);
    }
    __syncthreads();
    float* red = (float*)smem;          // reuse pipeline smem: [256 rows][2 wn]
    if ((lane & 3) == 0) {
#pragma unroll
        for (int mi = 0; mi < 4; mi++) {
            int rA = wm * 64 + mi * 16 + r;
            red[rA * 2 + wn]       = pA[mi];
            red[(rA + 8) * 2 + wn] = pB[mi];
        }
    }
    __syncthreads();
    {
        float sum = red[tid * 2] + red[tid * 2 + 1];
        g_part2[(size_t)blockIdx.x * N_ + m0 + tid] = sum;
    }
}

__global__ void final_kernel(const float* __restrict__ b2, float* __restrict__ out) {
    int i = blockIdx.x * 256 + threadIdx.x;
    float s = b2[0];
#pragma unroll
    for (int nb = 0; nb < 8; nb++) s += g_part2[(size_t)nb * N_ + i];
    out[i] = s;
}

// ---------------- host ----------------
typedef CUresult (CUDAAPI *EncodeFn)(
    CUtensorMap*, CUtensorMapDataType, cuuint32_t, void*,
    const cuuint64_t*, const cuuint64_t*, const cuuint32_t*, const cuuint32_t*,
    CUtensorMapInterleave, CUtensorMapSwizzle, CUtensorMapL2promotion, CUtensorMapFloatOOBfill);

static void encode2d(EncodeFn enc, CUtensorMap* m, void* ptr, uint64_t d0, uint64_t d1,
                     uint32_t rows) {
    cuuint64_t dims[2] = {d0, d1};
    cuuint64_t strides[1] = {d0 * 2};
    cuuint32_t box[2] = {64u, rows};   // 128B x rows, SW128
    cuuint32_t es[2] = {1u, 1u};
    enc(m, CU_TENSOR_MAP_DATA_TYPE_FLOAT16, 2, ptr, dims, strides, box, es,
        CU_TENSOR_MAP_INTERLEAVE_NONE, CU_TENSOR_MAP_SWIZZLE_128B,
        CU_TENSOR_MAP_L2_PROMOTION_L2_128B, CU_TENSOR_MAP_FLOAT_OOB_FILL_NONE);
}

extern "C" void kernel_launch(void* const* d_in, const int* in_sizes, int n_in,
                              void* d_out, int out_size) {
    const float* q     = (const float*)d_in[0];
    const float* k     = (const float*)d_in[1];
    const int*   bidx  = (const int*)d_in[2];
    const void*  mask  = d_in[3];
    const int*   count = (const int*)d_in[4];
    const float* W1    = (const float*)d_in[5];
    const float* b1    = (const float*)d_in[6];
    const float* W2    = (const float*)d_in[7];
    const float* b2    = (const float*)d_in[8];
    float* out = (float*)d_out;

    void* encp = nullptr;
    cudaDriverEntryPointQueryResult st;
    cudaGetDriverEntryPointByVersion("cuTensorMapEncodeTiled", &encp, 12000,
                                     cudaEnableDefault, &st);
    EncodeFn enc = (EncodeFn)encp;

    void *p_f, *p_w;
    cudaGetSymbolAddress(&p_f, g_feat);
    cudaGetSymbolAddress(&p_w, g_wt);

    CUtensorMap tm_a, tm_b;
    encode2d(enc, &tm_a, p_f, KTOT, N_, 256u);
    encode2d(enc, &tm_b, p_w, KTOT, HID_, 128u);

    cudaFuncSetAttribute(gemm_kernel, cudaFuncAttributeMaxDynamicSharedMemorySize, SMEM_ALLOC);

    detect_mask_kernel<<<1, 32>>>((const unsigned int*)mask);
    gather_idx_kernel<<<N_ / 8, 256>>>(mask);
    convert_feat_kernel<<<N_, 256>>>(q, k, bidx);
    convert_w1_kernel<<<dim3(KTOT / 32, HID_ / 32), dim3(32, 8)>>>(W1);
    gemm_kernel<<<dim3(HID_ / BN, N_ / BM), 256, SMEM_ALLOC>>>(tm_a, tm_b, W1, b1, W2, count);
    final_kernel<<<N_ / 256, 256>>>(b2, out);
}

// round 14
// speedup vs baseline: 8.1163x; 1.0303x over previous
#include <cuda.h>
#include <cuda_runtime.h>
#include <cuda_fp16.h>
#include <math.h>
#include <stdint.h>

#define B_ 64
#define L_ 256
#define D_ 128
#define N_ 8192
#define KEEP_ 64
#define HID_ 1024
#define KTOT 8320
#define BM 128
#define BN 128
#define BK 64
#define STAGES 3
#define KITER 130           // KTOT / BK
// stage: A 16KB, B 16KB
#define STG_BYTES 32768
#define A_OFF 0
#define B_OFF 16384
#define DATA_BYTES (STAGES * STG_BYTES)
#define SMEM_ALLOC (DATA_BYTES + 1024 + 128)

__device__ __align__(1024) __half g_feat[(size_t)N_ * KTOT];
__device__ __align__(1024) __half g_wt[(size_t)HID_ * KTOT];
__device__ int   g_idx[N_ * KEEP_];
__device__ float g_part2[8 * N_];
__device__ int   g_mask_mode;

// ---------------- PTX helpers ----------------
__device__ __forceinline__ uint32_t smem_to_u32(const void* p) {
    uint32_t a;
    asm("{ .reg .u64 t; cvta.to.shared.u64 t, %1; cvt.u32.u64 %0, t; }" : "=r"(a) : "l"(p));
    return a;
}
#define MBAR_INIT(a, c) asm volatile("mbarrier.init.shared.b64 [%0], %1;" :: "r"((uint32_t)(a)), "r"((uint32_t)(c)) : "memory")
#define MBAR_EXPECT(a, b) asm volatile("mbarrier.arrive.expect_tx.shared.b64 _, [%0], %1;" :: "r"((uint32_t)(a)), "r"((uint32_t)(b)) : "memory")
#define MBAR_WAIT(a, p) do { \
    uint32_t _m=(uint32_t)(a), _p=(uint32_t)(p); \
    asm volatile("{\n.reg .pred P;\nW%=:\nmbarrier.try_wait.parity.acquire.cta.shared::cta.b64 P, [%0], %1, 0x989680;\n@P bra.uni D%=;\nbra.uni W%=;\nD%=:\n}" :: "r"(_m), "r"(_p) : "memory"); \
} while(0)
#define FENCE_ASYNC() asm volatile("fence.proxy.async.shared::cta;" ::: "memory")
#define TMA_2D(dst, map, cx, cy, mbar) \
    asm volatile("cp.async.bulk.tensor.2d.shared::cta.global.tile.mbarrier::complete_tx::bytes " \
        "[%0], [%1, {%2, %3}], [%4];" \
        :: "r"((uint32_t)(dst)), "l"(map), "r"((int32_t)(cx)), "r"((int32_t)(cy)), "r"((uint32_t)(mbar)) : "memory")

__device__ __forceinline__ void ldsm4(uint32_t* r, uint32_t addr) {
    asm volatile("ldmatrix.sync.aligned.m8n8.x4.shared.b16 {%0,%1,%2,%3}, [%4];"
        : "=r"(r[0]), "=r"(r[1]), "=r"(r[2]), "=r"(r[3]) : "r"(addr));
}
__device__ __forceinline__ void mma_f16(float* d, const uint32_t* a, const uint32_t* b) {
    asm volatile("mma.sync.aligned.m16n8k16.row.col.f32.f16.f16.f32 "
        "{%0,%1,%2,%3}, {%4,%5,%6,%7}, {%8,%9}, {%0,%1,%2,%3};"
        : "+f"(d[0]), "+f"(d[1]), "+f"(d[2]), "+f"(d[3])
        : "r"(a[0]), "r"(a[1]), "r"(a[2]), "r"(a[3]), "r"(b[0]), "r"(b[1]));
}
// SW128: 16B chunk c (0..7) in a 128B row, tile 1KB-aligned -> c ^= (row & 7)
__device__ __forceinline__ uint32_t swz(int row, int c) {
    return (uint32_t)(row * 128 + ((c ^ (row & 7)) << 4));
}
__device__ __forceinline__ float gelu_exact(float x) {
    return 0.5f * x * (1.0f + erff(x * 0.7071067811865476f));
}

// ---------------- small kernels (proven) ----------------
__global__ void detect_mask_kernel(const unsigned int* __restrict__ mw) {
    if (threadIdx.x | blockIdx.x) return;
    bool i32ok = true, f32ok = true;
    for (int i = 0; i < 1024; i++) {
        unsigned w = mw[i];
        if (!(w == 0u || w == 1u)) i32ok = false;
        if (!(w == 0u || w == 0x3F800000u)) f32ok = false;
    }
    g_mask_mode = i32ok ? 1 : (f32ok ? 2 : 0);
}

__global__ void gather_idx_kernel(const void* __restrict__ maskp) {
    int gw = (blockIdx.x * blockDim.x + threadIdx.x) >> 5, lane = threadIdx.x & 31;
    if (gw >= N_) return;
    const int n = gw;
    g_idx[n * KEEP_ + lane] = -1;
    g_idx[n * KEEP_ + 32 + lane] = -1;
    __syncwarp();
    const int mode = g_mask_mode;
    const unsigned char* m8 = (const unsigned char*)maskp;
    const int* m32 = (const int*)maskp;
    const float* mf = (const float*)maskp;
    int base = 0;
    for (int g = 0; g < 8 && base < KEEP_; g++) {
        int pos = g * 32 + lane;
        bool m;
        if (mode == 1)      m = (m32[(size_t)n * L_ + pos] != 0);
        else if (mode == 2) m = (mf [(size_t)n * L_ + pos] != 0.0f);
        else                m = (m8 [(size_t)n * L_ + pos] != 0);
        unsigned bal = __ballot_sync(0xffffffffu, m);
        int slot = base + __popc(bal & ((1u << lane) - 1u));
        if (m && slot < KEEP_) g_idx[n * KEEP_ + slot] = pos;
        base += __popc(bal);
    }
}

__global__ void __launch_bounds__(256)
convert_feat_kernel(const float* __restrict__ q, const float* __restrict__ kmat,
                    const int* __restrict__ bidx) {
    int row = blockIdx.x;
    const int* idxr = g_idx + row * KEEP_;
    const float* kbase = kmat + (size_t)bidx[row] * (L_ * D_);
    size_t ro = (size_t)row * KTOT;
    for (int pos = threadIdx.x; pos < KTOT; pos += 256) {
        float v;
        if (pos < D_) v = q[(size_t)row * D_ + pos];
        else {
            int j = (pos - D_) >> 7, d = (pos - D_) & 127;
            int ix = idxr[j];
            v = (ix >= 0) ? kbase[(size_t)ix * D_ + d] : 0.0f;
        }
        g_feat[ro + pos] = __float2half_rn(v);
    }
}

__global__ void __launch_bounds__(256)
convert_w1_kernel(const float* __restrict__ W1) {
    __shared__ float t[32][33];
    int k0 = blockIdx.x * 32, n0 = blockIdx.y * 32;
    int tx = threadIdx.x, ty = threadIdx.y;  // 32 x 8
#pragma unroll
    for (int i = 0; i < 4; i++)
        t[ty + i * 8][tx] = W1[(size_t)(k0 + ty + i * 8) * HID_ + n0 + tx];
    __syncthreads();
#pragma unroll
    for (int i = 0; i < 4; i++) {
        int r = ty + i * 8;
        float v = t[tx][r];
        g_wt[(size_t)(n0 + r) * KTOT + k0 + tx] = __float2half_rn(v);
    }
}

// ---------------- fp16 mma.sync GEMM, TMA-fed, occupancy 2 ----------------
__global__ void __launch_bounds__(256, 2)
gemm_kernel(const __grid_constant__ CUtensorMap tm_a,
            const __grid_constant__ CUtensorMap tm_b,
            const float* __restrict__ W1, const float* __restrict__ b1,
            const float* __restrict__ W2, const int* __restrict__ count)
{
    extern __shared__ char smem[];
    const uint32_t sb = smem_to_u32(smem);
    const uint32_t db = (sb + 1023u) & ~1023u;          // data base, 1KB aligned
    const uint32_t mb = db + DATA_BYTES;                // 3 full mbarriers
    const int tid = threadIdx.x, lane = tid & 31, wid = tid >> 5;
    const int wm = wid >> 1, wn = wid & 1;              // 4 x 2 warps, 32x64 tiles
    const int m0 = blockIdx.y * BM, n0 = blockIdx.x * BN;

    if (tid == 0) {
#pragma unroll
        for (int s = 0; s < STAGES; s++) MBAR_INIT(mb + s * 8, 1);
        FENCE_ASYNC();
    }
    __syncthreads();

    if (tid == 0) {
#pragma unroll
        for (int s = 0; s < STAGES; s++) {
            uint32_t st = db + s * STG_BYTES;
            MBAR_EXPECT(mb + s * 8, STG_BYTES);
            TMA_2D(st + A_OFF, &tm_a, s * BK, m0, mb + s * 8);
            TMA_2D(st + B_OFF, &tm_b, s * BK, n0, mb + s * 8);
        }
    }

    float acc[2][8][4];
#pragma unroll
    for (int a = 0; a < 2; a++)
#pragma unroll
        for (int b = 0; b < 8; b++)
#pragma unroll
            for (int c = 0; c < 4; c++) acc[a][b][c] = 0.0f;

    int s = 0, phase = 0;
    for (int kt = 0; kt < KITER; kt++) {
        MBAR_WAIT(mb + s * 8, phase);
        const uint32_t stg = db + s * STG_BYTES;

#pragma unroll
        for (int ks = 0; ks < 4; ks++) {                // k16 steps within BK=64
            uint32_t af[2][4], bf[8][2];
            const int cb = ks * 2 + (lane >> 4);
#pragma unroll
            for (int mi = 0; mi < 2; mi++) {
                int row = wm * 32 + mi * 16 + (lane & 15);
                ldsm4(af[mi], stg + A_OFF + swz(row, cb));
            }
#pragma unroll
            for (int nj = 0; nj < 4; nj++) {
                int row = wn * 64 + nj * 16 + (lane & 15);
                uint32_t t[4];
                ldsm4(t, stg + B_OFF + swz(row, cb));
                bf[nj*2][0] = t[0]; bf[nj*2][1] = t[2];
                bf[nj*2+1][0] = t[1]; bf[nj*2+1][1] = t[3];
            }

            if (ks == 3) {
                __syncthreads();        // stage consumed; refill overlaps mma
                if (tid == 0 && kt + STAGES < KITER) {
                    int kn = kt + STAGES;
                    uint32_t st = db + s * STG_BYTES;
                    MBAR_EXPECT(mb + s * 8, STG_BYTES);
                    TMA_2D(st + A_OFF, &tm_a, kn * BK, m0, mb + s * 8);
                    TMA_2D(st + B_OFF, &tm_b, kn * BK, n0, mb + s * 8);
                }
            }
#pragma unroll
            for (int mi = 0; mi < 2; mi++)
#pragma unroll
                for (int ni = 0; ni < 8; ni++)
                    mma_f16(acc[mi][ni], af[mi], bf[ni]);
        }
        if (++s == STAGES) { s = 0; phase ^= 1; }
    }

    // ---- fused epilogue: z = acc + b1 + lc*W1[8320]; gelu(z)*W2 row-reduce ----
    const int r = lane >> 2, c2 = (lane & 3) * 2;
    const float* wl = W1 + (size_t)8320 * HID_;
    float pA[2], pB[2], lcA[2], lcB[2];
#pragma unroll
    for (int mi = 0; mi < 2; mi++) {
        int rowA = m0 + wm * 32 + mi * 16 + r;
        lcA[mi] = log1pf((float)count[rowA]);
        lcB[mi] = log1pf((float)count[rowA + 8]);
        pA[mi] = 0.0f; pB[mi] = 0.0f;
    }
#pragma unroll
    for (int ni = 0; ni < 8; ni++) {
        int n = n0 + wn * 64 + ni * 8 + c2;
        float b10 = b1[n], b11 = b1[n + 1];
        float wl0 = wl[n], wl1 = wl[n + 1];
        float w20 = W2[n], w21 = W2[n + 1];
#pragma unroll
        for (int mi = 0; mi < 2; mi++) {
            pA[mi] += gelu_exact(acc[mi][ni][0] + b10 + lcA[mi] * wl0) * w20
                    + gelu_exact(acc[mi][ni][1] + b11 + lcA[mi] * wl1) * w21;
            pB[mi] += gelu_exact(acc[mi][ni][2] + b10 + lcB[mi] * wl0) * w20
                    + gelu_exact(acc[mi][ni][3] + b11 + lcB[mi] * wl1) * w21;
        }
    }
#pragma unroll
    for (int mi = 0; mi < 2; mi++) {
        pA[mi] += __shfl_xor_sync(0xffffffffu, pA[mi], 1);
        pA[mi] += __shfl_xor_sync(0xffffffffu, pA[mi], 2);
        pB[mi] += __shfl_xor_sync(0xffffffffu, pB[mi], 1);
        pB[mi] += __shfl_xor_sync(0xffffffffu, pB[mi], 2);
    }
    __syncthreads();
    float* red = (float*)smem;          // reuse pipeline smem: [128 rows][2 wn]
    if ((lane & 3) == 0) {
#pragma unroll
        for (int mi = 0; mi < 2; mi++) {
            int rA = wm * 32 + mi * 16 + r;
            red[rA * 2 + wn]       = pA[mi];
            red[(rA + 8) * 2 + wn] = pB[mi];
        }
    }
    __syncthreads();
    if (tid < 128) {
        float sum = red[tid * 2] + red[tid * 2 + 1];
        g_part2[(size_t)blockIdx.x * N_ + m0 + tid] = sum;
    }
}

__global__ void final_kernel(const float* __restrict__ b2, float* __restrict__ out) {
    int i = blockIdx.x * 256 + threadIdx.x;
    float s = b2[0];
#pragma unroll
    for (int nb = 0; nb < 8; nb++) s += g_part2[(size_t)nb * N_ + i];
    out[i] = s;
}

// ---------------- host ----------------
typedef CUresult (CUDAAPI *EncodeFn)(
    CUtensorMap*, CUtensorMapDataType, cuuint32_t, void*,
    const cuuint64_t*, const cuuint64_t*, const cuuint32_t*, const cuuint32_t*,
    CUtensorMapInterleave, CUtensorMapSwizzle, CUtensorMapL2promotion, CUtensorMapFloatOOBfill);

static void encode2d(EncodeFn enc, CUtensorMap* m, void* ptr, uint64_t d0, uint64_t d1,
                     uint32_t rows) {
    cuuint64_t dims[2] = {d0, d1};
    cuuint64_t strides[1] = {d0 * 2};
    cuuint32_t box[2] = {64u, rows};   // 128B x rows, SW128
    cuuint32_t es[2] = {1u, 1u};
    enc(m, CU_TENSOR_MAP_DATA_TYPE_FLOAT16, 2, ptr, dims, strides, box, es,
        CU_TENSOR_MAP_INTERLEAVE_NONE, CU_TENSOR_MAP_SWIZZLE_128B,
        CU_TENSOR_MAP_L2_PROMOTION_L2_128B, CU_TENSOR_MAP_FLOAT_OOB_FILL_NONE);
}

extern "C" void kernel_launch(void* const* d_in, const int* in_sizes, int n_in,
                              void* d_out, int out_size) {
    const float* q     = (const float*)d_in[0];
    const float* k     = (const float*)d_in[1];
    const int*   bidx  = (const int*)d_in[2];
    const void*  mask  = d_in[3];
    const int*   count = (const int*)d_in[4];
    const float* W1    = (const float*)d_in[5];
    const float* b1    = (const float*)d_in[6];
    const float* W2    = (const float*)d_in[7];
    const float* b2    = (const float*)d_in[8];
    float* out = (float*)d_out;

    void* encp = nullptr;
    cudaDriverEntryPointQueryResult st;
    cudaGetDriverEntryPointByVersion("cuTensorMapEncodeTiled", &encp, 12000,
                                     cudaEnableDefault, &st);
    EncodeFn enc = (EncodeFn)encp;

    void *p_f, *p_w;
    cudaGetSymbolAddress(&p_f, g_feat);
    cudaGetSymbolAddress(&p_w, g_wt);

    CUtensorMap tm_a, tm_b;
    encode2d(enc, &tm_a, p_f, KTOT, N_, 128u);
    encode2d(enc, &tm_b, p_w, KTOT, HID_, 128u);

    cudaFuncSetAttribute(gemm_kernel, cudaFuncAttributeMaxDynamicSharedMemorySize, SMEM_ALLOC);

    detect_mask_kernel<<<1, 32>>>((const unsigned int*)mask);
    gather_idx_kernel<<<N_ / 8, 256>>>(mask);
    convert_feat_kernel<<<N_, 256>>>(q, k, bidx);
    convert_w1_kernel<<<dim3(KTOT / 32, HID_ / 32), dim3(32, 8)>>>(W1);
    gemm_kernel<<<dim3(HID_ / BN, N_ / BM), 256, SMEM_ALLOC>>>(tm_a, tm_b, W1, b1, W2, count);
    final_kernel<<<N_ / 256, 256>>>(b2, out);
}

// round 15
// speedup vs baseline: 8.7202x; 1.0744x over previous
#include <cuda.h>
#include <cuda_runtime.h>
#include <cuda_fp16.h>
#include <math.h>
#include <stdint.h>

#define B_ 64
#define L_ 256
#define D_ 128
#define N_ 8192
#define KEEP_ 64
#define HID_ 1024
#define KTOT 8320
#define BM 128
#define BN 128
#define BK 64
#define STAGES 3
#define KITER 130           // KTOT / BK
// stage: A 16KB, B 16KB
#define STG_BYTES 32768
#define A_OFF 0
#define B_OFF 16384
#define DATA_BYTES (STAGES * STG_BYTES)
#define SMEM_ALLOC (DATA_BYTES + 1024 + 128)

__device__ __align__(1024) __half g_feat[(size_t)N_ * KTOT];
__device__ __align__(1024) __half g_wt[(size_t)HID_ * KTOT];
__device__ float g_part2[8 * N_];
__device__ int   g_mask_mode;

// ---------------- PTX helpers ----------------
__device__ __forceinline__ uint32_t smem_to_u32(const void* p) {
    uint32_t a;
    asm("{ .reg .u64 t; cvta.to.shared.u64 t, %1; cvt.u32.u64 %0, t; }" : "=r"(a) : "l"(p));
    return a;
}
#define MBAR_INIT(a, c) asm volatile("mbarrier.init.shared.b64 [%0], %1;" :: "r"((uint32_t)(a)), "r"((uint32_t)(c)) : "memory")
#define MBAR_EXPECT(a, b) asm volatile("mbarrier.arrive.expect_tx.shared.b64 _, [%0], %1;" :: "r"((uint32_t)(a)), "r"((uint32_t)(b)) : "memory")
#define MBAR_WAIT(a, p) do { \
    uint32_t _m=(uint32_t)(a), _p=(uint32_t)(p); \
    asm volatile("{\n.reg .pred P;\nW%=:\nmbarrier.try_wait.parity.acquire.cta.shared::cta.b64 P, [%0], %1, 0x989680;\n@P bra.uni D%=;\nbra.uni W%=;\nD%=:\n}" :: "r"(_m), "r"(_p) : "memory"); \
} while(0)
#define FENCE_ASYNC() asm volatile("fence.proxy.async.shared::cta;" ::: "memory")
#define TMA_2D(dst, map, cx, cy, mbar) \
    asm volatile("cp.async.bulk.tensor.2d.shared::cta.global.tile.mbarrier::complete_tx::bytes " \
        "[%0], [%1, {%2, %3}], [%4];" \
        :: "r"((uint32_t)(dst)), "l"(map), "r"((int32_t)(cx)), "r"((int32_t)(cy)), "r"((uint32_t)(mbar)) : "memory")

__device__ __forceinline__ void ldsm4(uint32_t* r, uint32_t addr) {
    asm volatile("ldmatrix.sync.aligned.m8n8.x4.shared.b16 {%0,%1,%2,%3}, [%4];"
        : "=r"(r[0]), "=r"(r[1]), "=r"(r[2]), "=r"(r[3]) : "r"(addr));
}
__device__ __forceinline__ void mma_f16(float* d, const uint32_t* a, const uint32_t* b) {
    asm volatile("mma.sync.aligned.m16n8k16.row.col.f32.f16.f16.f32 "
        "{%0,%1,%2,%3}, {%4,%5,%6,%7}, {%8,%9}, {%0,%1,%2,%3};"
        : "+f"(d[0]), "+f"(d[1]), "+f"(d[2]), "+f"(d[3])
        : "r"(a[0]), "r"(a[1]), "r"(a[2]), "r"(a[3]), "r"(b[0]), "r"(b[1]));
}
// SW128: 16B chunk c (0..7) in a 128B row, tile 1KB-aligned -> c ^= (row & 7)
__device__ __forceinline__ uint32_t swz(int row, int c) {
    return (uint32_t)(row * 128 + ((c ^ (row & 7)) << 4));
}
__device__ __forceinline__ float gelu_exact(float x) {
    return 0.5f * x * (1.0f + erff(x * 0.7071067811865476f));
}

// ---------------- mask sniffer (proven) ----------------
__global__ void detect_mask_kernel(const unsigned int* __restrict__ mw) {
    if (threadIdx.x | blockIdx.x) return;
    bool i32ok = true, f32ok = true;
    for (int i = 0; i < 1024; i++) {
        unsigned w = mw[i];
        if (!(w == 0u || w == 1u)) i32ok = false;
        if (!(w == 0u || w == 0x3F800000u)) f32ok = false;
    }
    g_mask_mode = i32ok ? 1 : (f32ok ? 2 : 0);
}

// ---------------- fused gather + fp16 feat conversion, 8-wide ----------------
__global__ void __launch_bounds__(256)
fused_feat_kernel(const float* __restrict__ q, const float* __restrict__ kmat,
                  const int* __restrict__ bidx, const void* __restrict__ maskp) {
    __shared__ int sidx[KEEP_];
    const int row = blockIdx.x, tid = threadIdx.x, lane = tid & 31;

    if (tid < 32) {                           // warp 0: ballot compaction
        sidx[lane] = -1;
        sidx[32 + lane] = -1;
        const int mode = g_mask_mode;
        const unsigned char* m8 = (const unsigned char*)maskp;
        const int* m32 = (const int*)maskp;
        const float* mf = (const float*)maskp;
        int base = 0;
        for (int g = 0; g < 8 && base < KEEP_; g++) {
            int pos = g * 32 + lane;
            bool m;
            if (mode == 1)      m = (m32[(size_t)row * L_ + pos] != 0);
            else if (mode == 2) m = (mf [(size_t)row * L_ + pos] != 0.0f);
            else                m = (m8 [(size_t)row * L_ + pos] != 0);
            unsigned bal = __ballot_sync(0xffffffffu, m);
            int slot = base + __popc(bal & ((1u << lane) - 1u));
            if (m && slot < KEEP_) sidx[slot] = pos;
            base += __popc(bal);
        }
    }
    __syncthreads();

    const float* kbase = kmat + (size_t)bidx[row] * (L_ * D_);
    const float* qrow  = q + (size_t)row * D_;
    __half* dst = g_feat + (size_t)row * KTOT;
    for (int g = tid; g < KTOT / 8; g += 256) {       // 1040 groups of 8
        int pos = g * 8;
        const float* src;
        if (pos < D_) src = qrow + pos;
        else {
            int ix = sidx[(pos - D_) >> 7];
            src = (ix >= 0) ? kbase + (size_t)ix * D_ + ((pos - D_) & 127) : 0;
        }
        __half h[8];
        if (src) {
            float4 v0 = *(const float4*)(src);
            float4 v1 = *(const float4*)(src + 4);
            h[0] = __float2half_rn(v0.x); h[1] = __float2half_rn(v0.y);
            h[2] = __float2half_rn(v0.z); h[3] = __float2half_rn(v0.w);
            h[4] = __float2half_rn(v1.x); h[5] = __float2half_rn(v1.y);
            h[6] = __float2half_rn(v1.z); h[7] = __float2half_rn(v1.w);
        } else {
#pragma unroll
            for (int i = 0; i < 8; i++) h[i] = __float2half_rn(0.0f);
        }
        *(uint4*)(dst + pos) = *(const uint4*)h;
    }
}

// ---------------- W1 transpose to fp16, 16B stores ----------------
__global__ void __launch_bounds__(256)
convert_w1_kernel(const float* __restrict__ W1) {
    __shared__ float t[64][33];
    const int k0 = blockIdx.x * 64, n0 = blockIdx.y * 32;
    const int tid = threadIdx.x;
#pragma unroll
    for (int i = 0; i < 8; i++) {
        int idx = tid + i * 256;               // 2048 elems
        int kr = idx >> 5, nc = idx & 31;
        t[kr][nc] = W1[(size_t)(k0 + kr) * HID_ + n0 + nc];
    }
    __syncthreads();
    const int n = tid >> 3, gs = tid & 7;      // n-col 0..31, k-group 0..7
    __half h[8];
#pragma unroll
    for (int i = 0; i < 8; i++) h[i] = __float2half_rn(t[gs * 8 + i][n]);
    *(uint4*)(g_wt + (size_t)(n0 + n) * KTOT + k0 + gs * 8) = *(const uint4*)h;
}

// ---------------- fp16 mma.sync GEMM, TMA-fed, occupancy 2 (R14-proven) ----------------
__global__ void __launch_bounds__(256, 2)
gemm_kernel(const __grid_constant__ CUtensorMap tm_a,
            const __grid_constant__ CUtensorMap tm_b,
            const float* __restrict__ W1, const float* __restrict__ b1,
            const float* __restrict__ W2, const int* __restrict__ count)
{
    extern __shared__ char smem[];
    const uint32_t sb = smem_to_u32(smem);
    const uint32_t db = (sb + 1023u) & ~1023u;
    const uint32_t mb = db + DATA_BYTES;
    const int tid = threadIdx.x, lane = tid & 31, wid = tid >> 5;
    const int wm = wid >> 1, wn = wid & 1;              // 4 x 2 warps, 32x64 tiles
    const int m0 = blockIdx.y * BM, n0 = blockIdx.x * BN;

    if (tid == 0) {
#pragma unroll
        for (int s = 0; s < STAGES; s++) MBAR_INIT(mb + s * 8, 1);
        FENCE_ASYNC();
    }
    __syncthreads();

    if (tid == 0) {
#pragma unroll
        for (int s = 0; s < STAGES; s++) {
            uint32_t st = db + s * STG_BYTES;
            MBAR_EXPECT(mb + s * 8, STG_BYTES);
            TMA_2D(st + A_OFF, &tm_a, s * BK, m0, mb + s * 8);
            TMA_2D(st + B_OFF, &tm_b, s * BK, n0, mb + s * 8);
        }
    }

    float acc[2][8][4];
#pragma unroll
    for (int a = 0; a < 2; a++)
#pragma unroll
        for (int b = 0; b < 8; b++)
#pragma unroll
            for (int c = 0; c < 4; c++) acc[a][b][c] = 0.0f;

    int s = 0, phase = 0;
    for (int kt = 0; kt < KITER; kt++) {
        MBAR_WAIT(mb + s * 8, phase);
        const uint32_t stg = db + s * STG_BYTES;

#pragma unroll
        for (int ks = 0; ks < 4; ks++) {
            uint32_t af[2][4], bf[8][2];
            const int cb = ks * 2 + (lane >> 4);
#pragma unroll
            for (int mi = 0; mi < 2; mi++) {
                int row = wm * 32 + mi * 16 + (lane & 15);
                ldsm4(af[mi], stg + A_OFF + swz(row, cb));
            }
#pragma unroll
            for (int nj = 0; nj < 4; nj++) {
                int row = wn * 64 + nj * 16 + (lane & 15);
                uint32_t t[4];
                ldsm4(t, stg + B_OFF + swz(row, cb));
                bf[nj*2][0] = t[0]; bf[nj*2][1] = t[2];
                bf[nj*2+1][0] = t[1]; bf[nj*2+1][1] = t[3];
            }

            if (ks == 3) {
                __syncthreads();
                if (tid == 0 && kt + STAGES < KITER) {
                    int kn = kt + STAGES;
                    uint32_t st = db + s * STG_BYTES;
                    MBAR_EXPECT(mb + s * 8, STG_BYTES);
                    TMA_2D(st + A_OFF, &tm_a, kn * BK, m0, mb + s * 8);
                    TMA_2D(st + B_OFF, &tm_b, kn * BK, n0, mb + s * 8);
                }
            }
#pragma unroll
            for (int mi = 0; mi < 2; mi++)
#pragma unroll
                for (int ni = 0; ni < 8; ni++)
                    mma_f16(acc[mi][ni], af[mi], bf[ni]);
        }
        if (++s == STAGES) { s = 0; phase ^= 1; }
    }

    // ---- fused epilogue ----
    const int r = lane >> 2, c2 = (lane & 3) * 2;
    const float* wl = W1 + (size_t)8320 * HID_;
    float pA[2], pB[2], lcA[2], lcB[2];
#pragma unroll
    for (int mi = 0; mi < 2; mi++) {
        int rowA = m0 + wm * 32 + mi * 16 + r;
        lcA[mi] = log1pf((float)count[rowA]);
        lcB[mi] = log1pf((float)count[rowA + 8]);
        pA[mi] = 0.0f; pB[mi] = 0.0f;
    }
#pragma unroll
    for (int ni = 0; ni < 8; ni++) {
        int n = n0 + wn * 64 + ni * 8 + c2;
        float b10 = b1[n], b11 = b1[n + 1];
        float wl0 = wl[n], wl1 = wl[n + 1];
        float w20 = W2[n], w21 = W2[n + 1];
#pragma unroll
        for (int mi = 0; mi < 2; mi++) {
            pA[mi] += gelu_exact(acc[mi][ni][0] + b10 + lcA[mi] * wl0) * w20
                    + gelu_exact(acc[mi][ni][1] + b11 + lcA[mi] * wl1) * w21;
            pB[mi] += gelu_exact(acc[mi][ni][2] + b10 + lcB[mi] * wl0) * w20
                    + gelu_exact(acc[mi][ni][3] + b11 + lcB[mi] * wl1) * w21;
        }
    }
#pragma unroll
    for (int mi = 0; mi < 2; mi++) {
        pA[mi] += __shfl_xor_sync(0xffffffffu, pA[mi], 1);
        pA[mi] += __shfl_xor_sync(0xffffffffu, pA[mi], 2);
        pB[mi] += __shfl_xor_sync(0xffffffffu, pB[mi], 1);
        pB[mi] += __shfl_xor_sync(0xffffffffu, pB[mi], 2);
    }
    __syncthreads();
    float* red = (float*)smem;          // [128 rows][2 wn]
    if ((lane & 3) == 0) {
#pragma unroll
        for (int mi = 0; mi < 2; mi++) {
            int rA = wm * 32 + mi * 16 + r;
            red[rA * 2 + wn]       = pA[mi];
            red[(rA + 8) * 2 + wn] = pB[mi];
        }
    }
    __syncthreads();
    if (tid < 128) {
        float sum = red[tid * 2] + red[tid * 2 + 1];
        g_part2[(size_t)blockIdx.x * N_ + m0 + tid] = sum;
    }
}

__global__ void final_kernel(const float* __restrict__ b2, float* __restrict__ out) {
    int i = blockIdx.x * 256 + threadIdx.x;
    float s = b2[0];
#pragma unroll
    for (int nb = 0; nb < 8; nb++) s += g_part2[(size_t)nb * N_ + i];
    out[i] = s;
}

// ---------------- host ----------------
typedef CUresult (CUDAAPI *EncodeFn)(
    CUtensorMap*, CUtensorMapDataType, cuuint32_t, void*,
    const cuuint64_t*, const cuuint64_t*, const cuuint32_t*, const cuuint32_t*,
    CUtensorMapInterleave, CUtensorMapSwizzle, CUtensorMapL2promotion, CUtensorMapFloatOOBfill);

static void encode2d(EncodeFn enc, CUtensorMap* m, void* ptr, uint64_t d0, uint64_t d1,
                     uint32_t rows) {
    cuuint64_t dims[2] = {d0, d1};
    cuuint64_t strides[1] = {d0 * 2};
    cuuint32_t box[2] = {64u, rows};   // 128B x rows, SW128
    cuuint32_t es[2] = {1u, 1u};
    enc(m, CU_TENSOR_MAP_DATA_TYPE_FLOAT16, 2, ptr, dims, strides, box, es,
        CU_TENSOR_MAP_INTERLEAVE_NONE, CU_TENSOR_MAP_SWIZZLE_128B,
        CU_TENSOR_MAP_L2_PROMOTION_L2_128B, CU_TENSOR_MAP_FLOAT_OOB_FILL_NONE);
}

extern "C" void kernel_launch(void* const* d_in, const int* in_sizes, int n_in,
                              void* d_out, int out_size) {
    const float* q     = (const float*)d_in[0];
    const float* k     = (const float*)d_in[1];
    const int*   bidx  = (const int*)d_in[2];
    const void*  mask  = d_in[3];
    const int*   count = (const int*)d_in[4];
    const float* W1    = (const float*)d_in[5];
    const float* b1    = (const float*)d_in[6];
    const float* W2    = (const float*)d_in[7];
    const float* b2    = (const float*)d_in[8];
    float* out = (float*)d_out;

    void* encp = nullptr;
    cudaDriverEntryPointQueryResult st;
    cudaGetDriverEntryPointByVersion("cuTensorMapEncodeTiled", &encp, 12000,
                                     cudaEnableDefault, &st);
    EncodeFn enc = (EncodeFn)encp;

    void *p_f, *p_w;
    cudaGetSymbolAddress(&p_f, g_feat);
    cudaGetSymbolAddress(&p_w, g_wt);

    CUtensorMap tm_a, tm_b;
    encode2d(enc, &tm_a, p_f, KTOT, N_, 128u);
    encode2d(enc, &tm_b, p_w, KTOT, HID_, 128u);

    cudaFuncSetAttribute(gemm_kernel, cudaFuncAttributeMaxDynamicSharedMemorySize, SMEM_ALLOC);

    detect_mask_kernel<<<1, 32>>>((const unsigned int*)mask);
    fused_feat_kernel<<<N_, 256>>>(q, k, bidx, mask);
    convert_w1_kernel<<<dim3(KTOT / 64, HID_ / 32), 256>>>(W1);
    gemm_kernel<<<dim3(HID_ / BN, N_ / BM), 256, SMEM_ALLOC>>>(tm_a, tm_b, W1, b1, W2, count);
    final_kernel<<<N_ / 256, 256>>>(b2, out);
}

// round 16
// speedup vs baseline: 8.8451x; 1.0143x over previous
#include <cuda.h>
#include <cuda_runtime.h>
#include <cuda_fp16.h>
#include <math.h>
#include <stdint.h>

#define B_ 64
#define L_ 256
#define D_ 128
#define N_ 8192
#define KEEP_ 64
#define HID_ 1024
#define KTOT 8320
#define BM 128
#define BN 128
#define BK 64
#define STAGES 3
#define KITER 130           // KTOT / BK
// stage: A 16KB, B 16KB
#define STG_BYTES 32768
#define A_OFF 0
#define B_OFF 16384
#define DATA_BYTES (STAGES * STG_BYTES)
#define SMEM_ALLOC (DATA_BYTES + 1024 + 128)

__device__ __align__(1024) __half g_feat[(size_t)N_ * KTOT];
__device__ __align__(1024) __half g_wt[(size_t)HID_ * KTOT];
__device__ float g_part2[8 * N_];
__device__ int   g_mask_mode;

// ---------------- PTX helpers ----------------
__device__ __forceinline__ uint32_t smem_to_u32(const void* p) {
    uint32_t a;
    asm("{ .reg .u64 t; cvta.to.shared.u64 t, %1; cvt.u32.u64 %0, t; }" : "=r"(a) : "l"(p));
    return a;
}
#define MBAR_INIT(a, c) asm volatile("mbarrier.init.shared.b64 [%0], %1;" :: "r"((uint32_t)(a)), "r"((uint32_t)(c)) : "memory")
#define MBAR_EXPECT(a, b) asm volatile("mbarrier.arrive.expect_tx.shared.b64 _, [%0], %1;" :: "r"((uint32_t)(a)), "r"((uint32_t)(b)) : "memory")
#define MBAR_WAIT(a, p) do { \
    uint32_t _m=(uint32_t)(a), _p=(uint32_t)(p); \
    asm volatile("{\n.reg .pred P;\nW%=:\nmbarrier.try_wait.parity.acquire.cta.shared::cta.b64 P, [%0], %1, 0x989680;\n@P bra.uni D%=;\nbra.uni W%=;\nD%=:\n}" :: "r"(_m), "r"(_p) : "memory"); \
} while(0)
#define FENCE_ASYNC() asm volatile("fence.proxy.async.shared::cta;" ::: "memory")
#define TMA_2D(dst, map, cx, cy, mbar) \
    asm volatile("cp.async.bulk.tensor.2d.shared::cta.global.tile.mbarrier::complete_tx::bytes " \
        "[%0], [%1, {%2, %3}], [%4];" \
        :: "r"((uint32_t)(dst)), "l"(map), "r"((int32_t)(cx)), "r"((int32_t)(cy)), "r"((uint32_t)(mbar)) : "memory")

__device__ __forceinline__ void ldsm4(uint32_t* r, uint32_t addr) {
    asm volatile("ldmatrix.sync.aligned.m8n8.x4.shared.b16 {%0,%1,%2,%3}, [%4];"
        : "=r"(r[0]), "=r"(r[1]), "=r"(r[2]), "=r"(r[3]) : "r"(addr));
}
__device__ __forceinline__ void mma_f16(float* d, const uint32_t* a, const uint32_t* b) {
    asm volatile("mma.sync.aligned.m16n8k16.row.col.f32.f16.f16.f32 "
        "{%0,%1,%2,%3}, {%4,%5,%6,%7}, {%8,%9}, {%0,%1,%2,%3};"
        : "+f"(d[0]), "+f"(d[1]), "+f"(d[2]), "+f"(d[3])
        : "r"(a[0]), "r"(a[1]), "r"(a[2]), "r"(a[3]), "r"(b[0]), "r"(b[1]));
}
// SW128: 16B chunk c (0..7) in a 128B row, tile 1KB-aligned -> c ^= (row & 7)
__device__ __forceinline__ uint32_t swz(int row, int c) {
    return (uint32_t)(row * 128 + ((c ^ (row & 7)) << 4));
}
__device__ __forceinline__ float gelu_exact(float x) {
    return 0.5f * x * (1.0f + erff(x * 0.7071067811865476f));
}

// ---------------- mask sniffer (proven) ----------------
__global__ void detect_mask_kernel(const unsigned int* __restrict__ mw) {
    if (threadIdx.x | blockIdx.x) return;
    bool i32ok = true, f32ok = true;
    for (int i = 0; i < 1024; i++) {
        unsigned w = mw[i];
        if (!(w == 0u || w == 1u)) i32ok = false;
        if (!(w == 0u || w == 0x3F800000u)) f32ok = false;
    }
    g_mask_mode = i32ok ? 1 : (f32ok ? 2 : 0);
}

// ---------------- fused gather + fp16 feat conversion, 8-wide (proven) ----------------
__global__ void __launch_bounds__(256)
fused_feat_kernel(const float* __restrict__ q, const float* __restrict__ kmat,
                  const int* __restrict__ bidx, const void* __restrict__ maskp) {
    __shared__ int sidx[KEEP_];
    const int row = blockIdx.x, tid = threadIdx.x, lane = tid & 31;

    if (tid < 32) {
        sidx[lane] = -1;
        sidx[32 + lane] = -1;
        const int mode = g_mask_mode;
        const unsigned char* m8 = (const unsigned char*)maskp;
        const int* m32 = (const int*)maskp;
        const float* mf = (const float*)maskp;
        int base = 0;
        for (int g = 0; g < 8 && base < KEEP_; g++) {
            int pos = g * 32 + lane;
            bool m;
            if (mode == 1)      m = (m32[(size_t)row * L_ + pos] != 0);
            else if (mode == 2) m = (mf [(size_t)row * L_ + pos] != 0.0f);
            else                m = (m8 [(size_t)row * L_ + pos] != 0);
            unsigned bal = __ballot_sync(0xffffffffu, m);
            int slot = base + __popc(bal & ((1u << lane) - 1u));
            if (m && slot < KEEP_) sidx[slot] = pos;
            base += __popc(bal);
        }
    }
    __syncthreads();

    const float* kbase = kmat + (size_t)bidx[row] * (L_ * D_);
    const float* qrow  = q + (size_t)row * D_;
    __half* dst = g_feat + (size_t)row * KTOT;
    for (int g = tid; g < KTOT / 8; g += 256) {
        int pos = g * 8;
        const float* src;
        if (pos < D_) src = qrow + pos;
        else {
            int ix = sidx[(pos - D_) >> 7];
            src = (ix >= 0) ? kbase + (size_t)ix * D_ + ((pos - D_) & 127) : 0;
        }
        __half h[8];
        if (src) {
            float4 v0 = *(const float4*)(src);
            float4 v1 = *(const float4*)(src + 4);
            h[0] = __float2half_rn(v0.x); h[1] = __float2half_rn(v0.y);
            h[2] = __float2half_rn(v0.z); h[3] = __float2half_rn(v0.w);
            h[4] = __float2half_rn(v1.x); h[5] = __float2half_rn(v1.y);
            h[6] = __float2half_rn(v1.z); h[7] = __float2half_rn(v1.w);
        } else {
#pragma unroll
            for (int i = 0; i < 8; i++) h[i] = __float2half_rn(0.0f);
        }
        *(uint4*)(dst + pos) = *(const uint4*)h;
    }
}

// ---------------- W1 transpose to fp16, 16B stores (proven) ----------------
__global__ void __launch_bounds__(256)
convert_w1_kernel(const float* __restrict__ W1) {
    __shared__ float t[64][33];
    const int k0 = blockIdx.x * 64, n0 = blockIdx.y * 32;
    const int tid = threadIdx.x;
#pragma unroll
    for (int i = 0; i < 8; i++) {
        int idx = tid + i * 256;
        int kr = idx >> 5, nc = idx & 31;
        t[kr][nc] = W1[(size_t)(k0 + kr) * HID_ + n0 + nc];
    }
    __syncthreads();
    const int n = tid >> 3, gs = tid & 7;
    __half h[8];
#pragma unroll
    for (int i = 0; i < 8; i++) h[i] = __float2half_rn(t[gs * 8 + i][n]);
    *(uint4*)(g_wt + (size_t)(n0 + n) * KTOT + k0 + gs * 8) = *(const uint4*)h;
}

// ---------------- fp16 GEMM, TMA-fed, occ 2, per-warp ks rotation ----------------
__global__ void __launch_bounds__(256, 2)
gemm_kernel(const __grid_constant__ CUtensorMap tm_a,
            const __grid_constant__ CUtensorMap tm_b,
            const float* __restrict__ W1, const float* __restrict__ b1,
            const float* __restrict__ W2, const int* __restrict__ count)
{
    extern __shared__ char smem[];
    const uint32_t sb = smem_to_u32(smem);
    const uint32_t db = (sb + 1023u) & ~1023u;
    const uint32_t mb = db + DATA_BYTES;
    const int tid = threadIdx.x, lane = tid & 31, wid = tid >> 5;
    const int wm = wid >> 1, wn = wid & 1;              // 4 x 2 warps, 32x64 tiles
    const int m0 = blockIdx.y * BM, n0 = blockIdx.x * BN;

    if (tid == 0) {
#pragma unroll
        for (int s = 0; s < STAGES; s++) MBAR_INIT(mb + s * 8, 1);
        FENCE_ASYNC();
    }
    __syncthreads();

    if (tid == 0) {
#pragma unroll
        for (int s = 0; s < STAGES; s++) {
            uint32_t st = db + s * STG_BYTES;
            MBAR_EXPECT(mb + s * 8, STG_BYTES);
            TMA_2D(st + A_OFF, &tm_a, s * BK, m0, mb + s * 8);
            TMA_2D(st + B_OFF, &tm_b, s * BK, n0, mb + s * 8);
        }
    }

    float acc[2][8][4];
#pragma unroll
    for (int a = 0; a < 2; a++)
#pragma unroll
        for (int b = 0; b < 8; b++)
#pragma unroll
            for (int c = 0; c < 4; c++) acc[a][b][c] = 0.0f;

    int s = 0, phase = 0;
    for (int kt = 0; kt < KITER; kt++) {
        MBAR_WAIT(mb + s * 8, phase);
        const uint32_t stg = db + s * STG_BYTES;

#pragma unroll
        for (int ks = 0; ks < 4; ks++) {
            // per-warp ks rotation: breaks warp lockstep so LDSM phases of the
            // 4 warps/SMSP never coincide -> tensor pipe stays fed
            const int kse = (ks + wid) & 3;
            uint32_t af[2][4], bf[8][2];
            const int cb = kse * 2 + (lane >> 4);
#pragma unroll
            for (int mi = 0; mi < 2; mi++) {
                int row = wm * 32 + mi * 16 + (lane & 15);
                ldsm4(af[mi], stg + A_OFF + swz(row, cb));
            }
#pragma unroll
            for (int nj = 0; nj < 4; nj++) {
                int row = wn * 64 + nj * 16 + (lane & 15);
                uint32_t t[4];
                ldsm4(t, stg + B_OFF + swz(row, cb));
                bf[nj*2][0] = t[0]; bf[nj*2][1] = t[2];
                bf[nj*2+1][0] = t[1]; bf[nj*2+1][1] = t[3];
            }

            if (ks == 3) {
                __syncthreads();        // stage consumed; refill overlaps mma
                if (tid == 0 && kt + STAGES < KITER) {
                    int kn = kt + STAGES;
                    uint32_t st = db + s * STG_BYTES;
                    MBAR_EXPECT(mb + s * 8, STG_BYTES);
                    TMA_2D(st + A_OFF, &tm_a, kn * BK, m0, mb + s * 8);
                    TMA_2D(st + B_OFF, &tm_b, kn * BK, n0, mb + s * 8);
                }
            }
#pragma unroll
            for (int mi = 0; mi < 2; mi++)
#pragma unroll
                for (int ni = 0; ni < 8; ni++)
                    mma_f16(acc[mi][ni], af[mi], bf[ni]);
        }
        if (++s == STAGES) { s = 0; phase ^= 1; }
    }

    // ---- fused epilogue (proven) ----
    const int r = lane >> 2, c2 = (lane & 3) * 2;
    const float* wl = W1 + (size_t)8320 * HID_;
    float pA[2], pB[2], lcA[2], lcB[2];
#pragma unroll
    for (int mi = 0; mi < 2; mi++) {
        int rowA = m0 + wm * 32 + mi * 16 + r;
        lcA[mi] = log1pf((float)count[rowA]);
        lcB[mi] = log1pf((float)count[rowA + 8]);
        pA[mi] = 0.0f; pB[mi] = 0.0f;
    }
#pragma unroll
    for (int ni = 0; ni < 8; ni++) {
        int n = n0 + wn * 64 + ni * 8 + c2;
        float b10 = b1[n], b11 = b1[n + 1];
        float wl0 = wl[n], wl1 = wl[n + 1];
        float w20 = W2[n], w21 = W2[n + 1];
#pragma unroll
        for (int mi = 0; mi < 2; mi++) {
            pA[mi] += gelu_exact(acc[mi][ni][0] + b10 + lcA[mi] * wl0) * w20
                    + gelu_exact(acc[mi][ni][1] + b11 + lcA[mi] * wl1) * w21;
            pB[mi] += gelu_exact(acc[mi][ni][2] + b10 + lcB[mi] * wl0) * w20
                    + gelu_exact(acc[mi][ni][3] + b11 + lcB[mi] * wl1) * w21;
        }
    }
#pragma unroll
    for (int mi = 0; mi < 2; mi++) {
        pA[mi] += __shfl_xor_sync(0xffffffffu, pA[mi], 1);
        pA[mi] += __shfl_xor_sync(0xffffffffu, pA[mi], 2);
        pB[mi] += __shfl_xor_sync(0xffffffffu, pB[mi], 1);
        pB[mi] += __shfl_xor_sync(0xffffffffu, pB[mi], 2);
    }
    __syncthreads();
    float* red = (float*)smem;          // [128 rows][2 wn]
    if ((lane & 3) == 0) {
#pragma unroll
        for (int mi = 0; mi < 2; mi++) {
            int rA = wm * 32 + mi * 16 + r;
            red[rA * 2 + wn]       = pA[mi];
            red[(rA + 8) * 2 + wn] = pB[mi];
        }
    }
    __syncthreads();
    if (tid < 128) {
        float sum = red[tid * 2] + red[tid * 2 + 1];
        g_part2[(size_t)blockIdx.x * N_ + m0 + tid] = sum;
    }
}

__global__ void final_kernel(const float* __restrict__ b2, float* __restrict__ out) {
    int i = blockIdx.x * 256 + threadIdx.x;
    float s = b2[0];
#pragma unroll
    for (int nb = 0; nb < 8; nb++) s += g_part2[(size_t)nb * N_ + i];
    out[i] = s;
}

// ---------------- host ----------------
typedef CUresult (CUDAAPI *EncodeFn)(
    CUtensorMap*, CUtensorMapDataType, cuuint32_t, void*,
    const cuuint64_t*, const cuuint64_t*, const cuuint32_t*, const cuuint32_t*,
    CUtensorMapInterleave, CUtensorMapSwizzle, CUtensorMapL2promotion, CUtensorMapFloatOOBfill);

static void encode2d(EncodeFn enc, CUtensorMap* m, void* ptr, uint64_t d0, uint64_t d1,
                     uint32_t rows) {
    cuuint64_t dims[2] = {d0, d1};
    cuuint64_t strides[1] = {d0 * 2};
    cuuint32_t box[2] = {64u, rows};   // 128B x rows, SW128
    cuuint32_t es[2] = {1u, 1u};
    enc(m, CU_TENSOR_MAP_DATA_TYPE_FLOAT16, 2, ptr, dims, strides, box, es,
        CU_TENSOR_MAP_INTERLEAVE_NONE, CU_TENSOR_MAP_SWIZZLE_128B,
        CU_TENSOR_MAP_L2_PROMOTION_L2_128B, CU_TENSOR_MAP_FLOAT_OOB_FILL_NONE);
}

extern "C" void kernel_launch(void* const* d_in, const int* in_sizes, int n_in,
                              void* d_out, int out_size) {
    const float* q     = (const float*)d_in[0];
    const float* k     = (const float*)d_in[1];
    const int*   bidx  = (const int*)d_in[2];
    const void*  mask  = d_in[3];
    const int*   count = (const int*)d_in[4];
    const float* W1    = (const float*)d_in[5];
    const float* b1    = (const float*)d_in[6];
    const float* W2    = (const float*)d_in[7];
    const float* b2    = (const float*)d_in[8];
    float* out = (float*)d_out;

    void* encp = nullptr;
    cudaDriverEntryPointQueryResult st;
    cudaGetDriverEntryPointByVersion("cuTensorMapEncodeTiled", &encp, 12000,
                                     cudaEnableDefault, &st);
    EncodeFn enc = (EncodeFn)encp;

    void *p_f, *p_w;
    cudaGetSymbolAddress(&p_f, g_feat);
    cudaGetSymbolAddress(&p_w, g_wt);

    CUtensorMap tm_a, tm_b;
    encode2d(enc, &tm_a, p_f, KTOT, N_, 128u);
    encode2d(enc, &tm_b, p_w, KTOT, HID_, 128u);

    cudaFuncSetAttribute(gemm_kernel, cudaFuncAttributeMaxDynamicSharedMemorySize, SMEM_ALLOC);

    detect_mask_kernel<<<1, 32>>>((const unsigned int*)mask);
    fused_feat_kernel<<<N_, 256>>>(q, k, bidx, mask);
    convert_w1_kernel<<<dim3(KTOT / 64, HID_ / 32), 256>>>(W1);
    gemm_kernel<<<dim3(HID_ / BN, N_ / BM), 256, SMEM_ALLOC>>>(tm_a, tm_b, W1, b1, W2, count);
    final_kernel<<<N_ / 256, 256>>>(b2, out);
}

// round 17
// speedup vs baseline: 8.8945x; 1.0056x over previous
#include <cuda.h>
#include <cuda_runtime.h>
#include <cuda_fp16.h>
#include <math.h>
#include <stdint.h>

#define B_ 64
#define L_ 256
#define D_ 128
#define N_ 8192
#define KEEP_ 64
#define HID_ 1024
#define KTOT 8320
#define BM 128
#define BN 128
#define BK 64
#define STAGES 3
#define KITER 130           // KTOT / BK
// stage: A 16KB, B 16KB
#define STG_BYTES 32768
#define A_OFF 0
#define B_OFF 16384
#define DATA_BYTES (STAGES * STG_BYTES)
#define SMEM_ALLOC (DATA_BYTES + 1024 + 128)

__device__ __align__(1024) __half g_feat[(size_t)N_ * KTOT];
__device__ __align__(1024) __half g_wt[(size_t)HID_ * KTOT];
__device__ float g_part2[8 * N_];
__device__ int   g_mask_mode;

// ---------------- PTX helpers ----------------
__device__ __forceinline__ uint32_t smem_to_u32(const void* p) {
    uint32_t a;
    asm("{ .reg .u64 t; cvta.to.shared.u64 t, %1; cvt.u32.u64 %0, t; }" : "=r"(a) : "l"(p));
    return a;
}
#define MBAR_INIT(a, c) asm volatile("mbarrier.init.shared.b64 [%0], %1;" :: "r"((uint32_t)(a)), "r"((uint32_t)(c)) : "memory")
#define MBAR_EXPECT(a, b) asm volatile("mbarrier.arrive.expect_tx.shared.b64 _, [%0], %1;" :: "r"((uint32_t)(a)), "r"((uint32_t)(b)) : "memory")
#define MBAR_WAIT(a, p) do { \
    uint32_t _m=(uint32_t)(a), _p=(uint32_t)(p); \
    asm volatile("{\n.reg .pred P;\nW%=:\nmbarrier.try_wait.parity.acquire.cta.shared::cta.b64 P, [%0], %1, 0x989680;\n@P bra.uni D%=;\nbra.uni W%=;\nD%=:\n}" :: "r"(_m), "r"(_p) : "memory"); \
} while(0)
#define FENCE_ASYNC() asm volatile("fence.proxy.async.shared::cta;" ::: "memory")
#define TMA_2D(dst, map, cx, cy, mbar) \
    asm volatile("cp.async.bulk.tensor.2d.shared::cta.global.tile.mbarrier::complete_tx::bytes " \
        "[%0], [%1, {%2, %3}], [%4];" \
        :: "r"((uint32_t)(dst)), "l"(map), "r"((int32_t)(cx)), "r"((int32_t)(cy)), "r"((uint32_t)(mbar)) : "memory")

__device__ __forceinline__ void ldsm4(uint32_t* r, uint32_t addr) {
    asm volatile("ldmatrix.sync.aligned.m8n8.x4.shared.b16 {%0,%1,%2,%3}, [%4];"
        : "=r"(r[0]), "=r"(r[1]), "=r"(r[2]), "=r"(r[3]) : "r"(addr));
}
__device__ __forceinline__ void mma_f16_d(float* d, const uint32_t* a, uint32_t b0, uint32_t b1) {
    asm volatile("mma.sync.aligned.m16n8k16.row.col.f32.f16.f16.f32 "
        "{%0,%1,%2,%3}, {%4,%5,%6,%7}, {%8,%9}, {%0,%1,%2,%3};"
        : "+f"(d[0]), "+f"(d[1]), "+f"(d[2]), "+f"(d[3])
        : "r"(a[0]), "r"(a[1]), "r"(a[2]), "r"(a[3]), "r"(b0), "r"(b1));
}
// SW128 xor-base: swz(row,c) = (row*128 + ((row&7)<<4)) ^ (c<<4)
__device__ __forceinline__ uint32_t swz_base(int row) {
    return (uint32_t)(row * 128 + ((row & 7) << 4));
}
__device__ __forceinline__ uint32_t swz(int row, int c) {
    return (uint32_t)(row * 128 + ((c ^ (row & 7)) << 4));
}
__device__ __forceinline__ float gelu_exact(float x) {
    return 0.5f * x * (1.0f + erff(x * 0.7071067811865476f));
}

// ---------------- mask sniffer (proven) ----------------
__global__ void detect_mask_kernel(const unsigned int* __restrict__ mw) {
    if (threadIdx.x | blockIdx.x) return;
    bool i32ok = true, f32ok = true;
    for (int i = 0; i < 1024; i++) {
        unsigned w = mw[i];
        if (!(w == 0u || w == 1u)) i32ok = false;
        if (!(w == 0u || w == 0x3F800000u)) f32ok = false;
    }
    g_mask_mode = i32ok ? 1 : (f32ok ? 2 : 0);
}

// ---------------- fused gather + fp16 feat conversion, 8-wide (proven) ----------------
__global__ void __launch_bounds__(256)
fused_feat_kernel(const float* __restrict__ q, const float* __restrict__ kmat,
                  const int* __restrict__ bidx, const void* __restrict__ maskp) {
    __shared__ int sidx[KEEP_];
    const int row = blockIdx.x, tid = threadIdx.x, lane = tid & 31;

    if (tid < 32) {
        sidx[lane] = -1;
        sidx[32 + lane] = -1;
        const int mode = g_mask_mode;
        const unsigned char* m8 = (const unsigned char*)maskp;
        const int* m32 = (const int*)maskp;
        const float* mf = (const float*)maskp;
        int base = 0;
        for (int g = 0; g < 8 && base < KEEP_; g++) {
            int pos = g * 32 + lane;
            bool m;
            if (mode == 1)      m = (m32[(size_t)row * L_ + pos] != 0);
            else if (mode == 2) m = (mf [(size_t)row * L_ + pos] != 0.0f);
            else                m = (m8 [(size_t)row * L_ + pos] != 0);
            unsigned bal = __ballot_sync(0xffffffffu, m);
            int slot = base + __popc(bal & ((1u << lane) - 1u));
            if (m && slot < KEEP_) sidx[slot] = pos;
            base += __popc(bal);
        }
    }
    __syncthreads();

    const float* kbase = kmat + (size_t)bidx[row] * (L_ * D_);
    const float* qrow  = q + (size_t)row * D_;
    __half* dst = g_feat + (size_t)row * KTOT;
    for (int g = tid; g < KTOT / 8; g += 256) {
        int pos = g * 8;
        const float* src;
        if (pos < D_) src = qrow + pos;
        else {
            int ix = sidx[(pos - D_) >> 7];
            src = (ix >= 0) ? kbase + (size_t)ix * D_ + ((pos - D_) & 127) : 0;
        }
        __half h[8];
        if (src) {
            float4 v0 = *(const float4*)(src);
            float4 v1 = *(const float4*)(src + 4);
            h[0] = __float2half_rn(v0.x); h[1] = __float2half_rn(v0.y);
            h[2] = __float2half_rn(v0.z); h[3] = __float2half_rn(v0.w);
            h[4] = __float2half_rn(v1.x); h[5] = __float2half_rn(v1.y);
            h[6] = __float2half_rn(v1.z); h[7] = __float2half_rn(v1.w);
        } else {
#pragma unroll
            for (int i = 0; i < 8; i++) h[i] = __float2half_rn(0.0f);
        }
        *(uint4*)(dst + pos) = *(const uint4*)h;
    }
}

// ---------------- W1 transpose to fp16, 16B stores (proven) ----------------
__global__ void __launch_bounds__(256)
convert_w1_kernel(const float* __restrict__ W1) {
    __shared__ float t[64][33];
    const int k0 = blockIdx.x * 64, n0 = blockIdx.y * 32;
    const int tid = threadIdx.x;
#pragma unroll
    for (int i = 0; i < 8; i++) {
        int idx = tid + i * 256;
        int kr = idx >> 5, nc = idx & 31;
        t[kr][nc] = W1[(size_t)(k0 + kr) * HID_ + n0 + nc];
    }
    __syncthreads();
    const int n = tid >> 3, gs = tid & 7;
    __half h[8];
#pragma unroll
    for (int i = 0; i < 8; i++) h[i] = __float2half_rn(t[gs * 8 + i][n]);
    *(uint4*)(g_wt + (size_t)(n0 + n) * KTOT + k0 + gs * 8) = *(const uint4*)h;
}

// ---------------- fp16 GEMM, TMA-fed, occ 2, strength-reduced addressing ----------------
__global__ void __launch_bounds__(256, 2)
gemm_kernel(const __grid_constant__ CUtensorMap tm_a,
            const __grid_constant__ CUtensorMap tm_b,
            const float* __restrict__ W1, const float* __restrict__ b1,
            const float* __restrict__ W2, const int* __restrict__ count)
{
    extern __shared__ char smem[];
    const uint32_t sb = smem_to_u32(smem);
    const uint32_t db = (sb + 1023u) & ~1023u;
    const uint32_t mb = db + DATA_BYTES;
    const int tid = threadIdx.x, lane = tid & 31, wid = tid >> 5;
    const int wm = wid >> 1, wn = wid & 1;              // 4 x 2 warps, 32x64 tiles
    const int m0 = blockIdx.y * BM, n0 = blockIdx.x * BN;

    if (tid == 0) {
#pragma unroll
        for (int s = 0; s < STAGES; s++) MBAR_INIT(mb + s * 8, 1);
        FENCE_ASYNC();
    }
    __syncthreads();

    if (tid == 0) {
#pragma unroll
        for (int s = 0; s < STAGES; s++) {
            uint32_t st = db + s * STG_BYTES;
            MBAR_EXPECT(mb + s * 8, STG_BYTES);
            TMA_2D(st + A_OFF, &tm_a, s * BK, m0, mb + s * 8);
            TMA_2D(st + B_OFF, &tm_b, s * BK, n0, mb + s * 8);
        }
    }

    // loop-invariant xor-bases for all 6 LDSM rows of this thread
    const uint32_t l4 = (uint32_t)((lane >> 4) << 4);
    uint32_t abase[2], bbase[4];
#pragma unroll
    for (int mi = 0; mi < 2; mi++)
        abase[mi] = A_OFF + swz_base(wm * 32 + mi * 16 + (lane & 15));
#pragma unroll
    for (int nj = 0; nj < 4; nj++)
        bbase[nj] = B_OFF + swz_base(wn * 64 + nj * 16 + (lane & 15));

    float acc[2][8][4];
#pragma unroll
    for (int a = 0; a < 2; a++)
#pragma unroll
        for (int b = 0; b < 8; b++)
#pragma unroll
            for (int c = 0; c < 4; c++) acc[a][b][c] = 0.0f;

    int s = 0, phase = 0;
    for (int kt = 0; kt < KITER; kt++) {
        MBAR_WAIT(mb + s * 8, phase);
        const uint32_t stg = db + s * STG_BYTES;

#pragma unroll
        for (int ks = 0; ks < 4; ks++) {
            const int kse = (ks + wid) & 3;             // per-warp rotation (R16)
            const uint32_t cbx = (uint32_t)(kse * 32) + l4;
            uint32_t af[2][4], bt[4][4];
#pragma unroll
            for (int mi = 0; mi < 2; mi++)
                ldsm4(af[mi], stg + (abase[mi] ^ cbx));
#pragma unroll
            for (int nj = 0; nj < 4; nj++)
                ldsm4(bt[nj], stg + (bbase[nj] ^ cbx));

            if (ks == 3) {
                __syncthreads();        // stage consumed; refill overlaps mma
                if (tid == 0 && kt + STAGES < KITER) {
                    int kn = kt + STAGES;
                    uint32_t st = db + s * STG_BYTES;
                    MBAR_EXPECT(mb + s * 8, STG_BYTES);
                    TMA_2D(st + A_OFF, &tm_a, kn * BK, m0, mb + s * 8);
                    TMA_2D(st + B_OFF, &tm_b, kn * BK, n0, mb + s * 8);
                }
            }
#pragma unroll
            for (int mi = 0; mi < 2; mi++)
#pragma unroll
                for (int nj = 0; nj < 4; nj++) {
                    mma_f16_d(acc[mi][nj * 2],     af[mi], bt[nj][0], bt[nj][2]);
                    mma_f16_d(acc[mi][nj * 2 + 1], af[mi], bt[nj][1], bt[nj][3]);
                }
        }
        if (++s == STAGES) { s = 0; phase ^= 1; }
    }

    // ---- fused epilogue (proven) ----
    const int r = lane >> 2, c2 = (lane & 3) * 2;
    const float* wl = W1 + (size_t)8320 * HID_;
    float pA[2], pB[2], lcA[2], lcB[2];
#pragma unroll
    for (int mi = 0; mi < 2; mi++) {
        int rowA = m0 + wm * 32 + mi * 16 + r;
        lcA[mi] = log1pf((float)count[rowA]);
        lcB[mi] = log1pf((float)count[rowA + 8]);
        pA[mi] = 0.0f; pB[mi] = 0.0f;
    }
#pragma unroll
    for (int ni = 0; ni < 8; ni++) {
        int n = n0 + wn * 64 + ni * 8 + c2;
        float b10 = b1[n], b11 = b1[n + 1];
        float wl0 = wl[n], wl1 = wl[n + 1];
        float w20 = W2[n], w21 = W2[n + 1];
#pragma unroll
        for (int mi = 0; mi < 2; mi++) {
            pA[mi] += gelu_exact(acc[mi][ni][0] + b10 + lcA[mi] * wl0) * w20
                    + gelu_exact(acc[mi][ni][1] + b11 + lcA[mi] * wl1) * w21;
            pB[mi] += gelu_exact(acc[mi][ni][2] + b10 + lcB[mi] * wl0) * w20
                    + gelu_exact(acc[mi][ni][3] + b11 + lcB[mi] * wl1) * w21;
        }
    }
#pragma unroll
    for (int mi = 0; mi < 2; mi++) {
        pA[mi] += __shfl_xor_sync(0xffffffffu, pA[mi], 1);
        pA[mi] += __shfl_xor_sync(0xffffffffu, pA[mi], 2);
        pB[mi] += __shfl_xor_sync(0xffffffffu, pB[mi], 1);
        pB[mi] += __shfl_xor_sync(0xffffffffu, pB[mi], 2);
    }
    __syncthreads();
    float* red = (float*)smem;          // [128 rows][2 wn]
    if ((lane & 3) == 0) {
#pragma unroll
        for (int mi = 0; mi < 2; mi++) {
            int rA = wm * 32 + mi * 16 + r;
            red[rA * 2 + wn]       = pA[mi];
            red[(rA + 8) * 2 + wn] = pB[mi];
        }
    }
    __syncthreads();
    if (tid < 128) {
        float sum = red[tid * 2] + red[tid * 2 + 1];
        g_part2[(size_t)blockIdx.x * N_ + m0 + tid] = sum;
    }
}

__global__ void final_kernel(const float* __restrict__ b2, float* __restrict__ out) {
    int i = blockIdx.x * 256 + threadIdx.x;
    float s = b2[0];
#pragma unroll
    for (int nb = 0; nb < 8; nb++) s += g_part2[(size_t)nb * N_ + i];
    out[i] = s;
}

// ---------------- host ----------------
typedef CUresult (CUDAAPI *EncodeFn)(
    CUtensorMap*, CUtensorMapDataType, cuuint32_t, void*,
    const cuuint64_t*, const cuuint64_t*, const cuuint32_t*, const cuuint32_t*,
    CUtensorMapInterleave, CUtensorMapSwizzle, CUtensorMapL2promotion, CUtensorMapFloatOOBfill);

static void encode2d(EncodeFn enc, CUtensorMap* m, void* ptr, uint64_t d0, uint64_t d1,
                     uint32_t rows) {
    cuuint64_t dims[2] = {d0, d1};
    cuuint64_t strides[1] = {d0 * 2};
    cuuint32_t box[2] = {64u, rows};   // 128B x rows, SW128
    cuuint32_t es[2] = {1u, 1u};
    enc(m, CU_TENSOR_MAP_DATA_TYPE_FLOAT16, 2, ptr, dims, strides, box, es,
        CU_TENSOR_MAP_INTERLEAVE_NONE, CU_TENSOR_MAP_SWIZZLE_128B,
        CU_TENSOR_MAP_L2_PROMOTION_L2_128B, CU_TENSOR_MAP_FLOAT_OOB_FILL_NONE);
}

extern "C" void kernel_launch(void* const* d_in, const int* in_sizes, int n_in,
                              void* d_out, int out_size) {
    const float* q     = (const float*)d_in[0];
    const float* k     = (const float*)d_in[1];
    const int*   bidx  = (const int*)d_in[2];
    const void*  mask  = d_in[3];
    const int*   count = (const int*)d_in[4];
    const float* W1    = (const float*)d_in[5];
    const float* b1    = (const float*)d_in[6];
    const float* W2    = (const float*)d_in[7];
    const float* b2    = (const float*)d_in[8];
    float* out = (float*)d_out;

    void* encp = nullptr;
    cudaDriverEntryPointQueryResult st;
    cudaGetDriverEntryPointByVersion("cuTensorMapEncodeTiled", &encp, 12000,
                                     cudaEnableDefault, &st);
    EncodeFn enc = (EncodeFn)encp;

    void *p_f, *p_w;
    cudaGetSymbolAddress(&p_f, g_feat);
    cudaGetSymbolAddress(&p_w, g_wt);

    CUtensorMap tm_a, tm_b;
    encode2d(enc, &tm_a, p_f, KTOT, N_, 128u);
    encode2d(enc, &tm_b, p_w, KTOT, HID_, 128u);

    cudaFuncSetAttribute(gemm_kernel, cudaFuncAttributeMaxDynamicSharedMemorySize, SMEM_ALLOC);

    detect_mask_kernel<<<1, 32>>>((const unsigned int*)mask);
    fused_feat_kernel<<<N_, 256>>>(q, k, bidx, mask);
    convert_w1_kernel<<<dim3(KTOT / 64, HID_ / 32), 256>>>(W1);
    gemm_kernel<<<dim3(HID_ / BN, N_ / BM), 256, SMEM_ALLOC>>>(tm_a, tm_b, W1, b1, W2, count);
    final_kernel<<<N_ / 256, 256>>>(b2, out);
}